// round 11
// baseline (speedup 1.0000x reference)
#include <cuda_runtime.h>

#define NPATHS 100000
#define NLINKS 10000

// ---------------- persistent device state ----------------
__device__ __align__(16) float g_link_state[NLINKS * 32];
__device__ __align__(16) float g_path_state[NPATHS * 32];
__device__ __align__(16) float g_m[NLINKS * 32];          // segment sums
__device__ __align__(16) float g_LG[NLINKS * 128];        // [link][lane][{z,r,h,pad}]

// ---------------- packed f32x2 helpers ----------------
typedef unsigned long long u64;

__device__ __forceinline__ u64 splat2(float x) {
    u64 r; asm("mov.b64 %0, {%1, %1};" : "=l"(r) : "f"(x)); return r;
}
__device__ __forceinline__ u64 pack2(float a, float b) {
    u64 r; asm("mov.b64 %0, {%1, %2};" : "=l"(r) : "f"(a), "f"(b)); return r;
}
__device__ __forceinline__ void unpack2(u64 v, float& a, float& b) {
    asm("mov.b64 {%0, %1}, %2;" : "=f"(a), "=f"(b) : "l"(v));
}
__device__ __forceinline__ void ffma2(u64& d, u64 a, u64 b) {
    asm("fma.rn.f32x2 %0, %1, %2, %0;" : "+l"(d) : "l"(a), "l"(b));
}
__device__ __forceinline__ void lds_v2(unsigned addr, u64& a, u64& b) {
    asm volatile("ld.shared.v2.u64 {%0, %1}, [%2];" : "=l"(a), "=l"(b) : "r"(addr));
}
__device__ __forceinline__ void sts_v2(unsigned addr, u64 a, u64 b) {
    asm volatile("st.shared.v2.u64 [%0], {%1, %2};" :: "r"(addr), "l"(a), "l"(b) : "memory");
}
__device__ __forceinline__ void ldg_v2(const void* p, u64& a, u64& b) {
    asm volatile("ld.global.nc.v2.u64 {%0, %1}, [%2];" : "=l"(a), "=l"(b) : "l"(p));
}

// ---------------- fast activations ----------------
__device__ __forceinline__ float tanh_ap(float x) {
    float r; asm("tanh.approx.f32 %0, %1;" : "=f"(r) : "f"(x)); return r;
}
__device__ __forceinline__ float sigmoid_t(float x) {
    return fmaf(tanh_ap(0.5f * x), 0.5f, 0.5f);
}
__device__ __forceinline__ float seluf_(float x) {
    const float sc = 1.0507009873554805f;
    const float al = 1.6732632423543772f;
    return x > 0.0f ? sc * x : sc * al * (__expf(x) - 1.0f);
}

// ---------------- init: states, m=0, initial LG (interleaved) ---------------
__global__ void k_init(const float* __restrict__ cap, const float* __restrict__ traffic,
                       const float* __restrict__ Wp, const float* __restrict__ bp) {
    int idx = blockIdx.x * blockDim.x + threadIdx.x;
    if (idx < NPATHS * 32)
        g_path_state[idx] = ((idx & 31) == 0) ? traffic[idx >> 5] : 0.0f;
    if (idx < NLINKS * 32) {
        g_link_state[idx] = ((idx & 31) == 0) ? cap[idx >> 5] : 0.0f;
        g_m[idx] = 0.0f;
    }
    if (idx < NLINKS * 128) {
        int l = idx >> 7;
        int jj = idx & 127;
        int lane = jj >> 2;           // 0..31
        int comp = jj & 3;            // 0=z,1=r,2=h,3=pad
        float v = 0.0f;
        if (comp < 3) {
            int col = comp * 32 + lane;       // column in [0,96)
            v = cap[l] * Wp[col] + bp[col];   // input bias bp[0]
            if (comp < 2) v += bp[96 + col];  // fold recurrent bias for z,r
        }
        g_LG[idx] = v;
    }
}

// ---------------- path phase v8: lane=dim, warp=16 paths --------------------
// single LDG.128 gather per path (interleaved LG), swizzled u64 h tile,
// tanh.approx gates, 6 blocks/SM.
#define PPW 16          // paths per warp
#define NPAIR 8         // path pairs per warp
#define HSTRB 80u       // bytes per dim row (10 u64: 4 groups x 16B + 16B pad)

__global__ void __launch_bounds__(128, 6)
k_path(const int* __restrict__ links, const float* __restrict__ Up,
       const float* __restrict__ bp) {
    __shared__ __align__(16) float sUp[3072];            // Up [k][j] row-major f32
    __shared__ int slinks[64 * 8];                       // 64 paths per block
    __shared__ __align__(16) char shtile[4 * 32 * HSTRB];// per warp: h[dim][group swz]

    const int tid  = threadIdx.x;
    const int lane = tid & 31;
    const int warp = tid >> 5;
    const int p0   = blockIdx.x * 64;                    // 64 paths per block

    for (int i = tid; i < 3072; i += 128) sUp[i] = Up[i];
    for (int i = tid; i < 512; i += 128) {
        int e = p0 * 8 + i;
        slinks[i] = (e < NPATHS * 8) ? links[e] : 0;
    }
    __syncthreads();

    const int pw = p0 + warp * PPW;
    if (pw >= NPATHS) return;                            // whole-warp exit

    char* shw = shtile + warp * 32 * HSTRB;
    float* shwf = reinterpret_cast<float*>(shw);
    const unsigned shw_a = (unsigned)__cvta_generic_to_shared(shw);
    const unsigned sl16 = ((unsigned)(lane >> 3) & 3u) * 16u;   // owner-dim swizzle (bytes)

    // initial h load: float slot = lane*20 + (((i>>2)*4) ^ (sl16>>2)) + (i&3)
    #pragma unroll 1
    for (int i = 0; i < PPW; i++)
        shwf[lane * 20 + ((((unsigned)i >> 2) * 4u) ^ (sl16 >> 2)) + (i & 3)] =
            g_path_state[(pw + i) * 32 + lane];
    __syncwarp();

    const u64 b1h2 = splat2(__ldg(bp + 96 + 64 + lane));
    const int* slk = slinks + warp * PPW * 8;
    const float4* lg4 = reinterpret_cast<const float4*>(g_LG) + lane;

    #pragma unroll 1
    for (int s = 0; s < 8; s++) {
        // prologue: 16 LDG.128 (one per path); z/r folded into acc init, h kept
        float4 pf[PPW];
        #pragma unroll
        for (int q = 0; q < PPW; q++)
            pf[q] = __ldg(lg4 + slk[q * 8 + s] * 32);

        u64 accz[NPAIR], accr[NPAIR], acch[NPAIR];
        float ph[PPW];
        #pragma unroll
        for (int p2 = 0; p2 < NPAIR; p2++) {
            accz[p2] = pack2(pf[2 * p2].x, pf[2 * p2 + 1].x);
            accr[p2] = pack2(pf[2 * p2].y, pf[2 * p2 + 1].y);
            acch[p2] = b1h2;
            ph[2 * p2]     = pf[2 * p2].z;
            ph[2 * p2 + 1] = pf[2 * p2 + 1].z;
        }

        // recurrent matvec: acc += h @ Up
        #pragma unroll 2
        for (int k = 0; k < 32; k++) {
            const float* w = sUp + k * 96 + lane;
            u64 wz2 = splat2(w[0]);
            u64 wr2 = splat2(w[32]);
            u64 wh2 = splat2(w[64]);
            unsigned ha = shw_a + (unsigned)k * HSTRB;
            unsigned sk16 = ((unsigned)(k >> 3) & 3u) * 16u;
            #pragma unroll
            for (int g = 0; g < 4; g++) {
                u64 hA, hB;
                lds_v2(ha + (((unsigned)g * 16u) ^ sk16), hA, hB);
                ffma2(accz[2*g],   hA, wz2);
                ffma2(accz[2*g+1], hB, wz2);
                ffma2(accr[2*g],   hA, wr2);
                ffma2(accr[2*g+1], hB, wr2);
                ffma2(acch[2*g],   hA, wh2);
                ffma2(acch[2*g+1], hB, wh2);
            }
        }

        // epilogue: gates, state update, coalesced scatter
        #pragma unroll
        for (int g = 0; g < 4; g++) {
            const int q0 = 4 * g;
            unsigned ea = shw_a + (unsigned)lane * HSTRB + (((unsigned)g * 16u) ^ sl16);
            u64 hoA2, hoB2;
            lds_v2(ea, hoA2, hoB2);
            float ho0, ho1, ho2, ho3;
            unpack2(hoA2, ho0, ho1);
            unpack2(hoB2, ho2, ho3);

            float az0, az1, az2v, az3, ar0, ar1, ar2v, ar3, ah0, ah1, ah2v, ah3;
            unpack2(accz[2*g], az0, az1);   unpack2(accz[2*g+1], az2v, az3);
            unpack2(accr[2*g], ar0, ar1);   unpack2(accr[2*g+1], ar2v, ar3);
            unpack2(acch[2*g], ah0, ah1);   unpack2(acch[2*g+1], ah2v, ah3);

            float z0 = sigmoid_t(az0);
            float r0 = sigmoid_t(ar0);
            float c0 = tanh_ap(ph[q0] + r0 * ah0);
            float hn0 = c0 + z0 * (ho0 - c0);

            float z1 = sigmoid_t(az1);
            float r1 = sigmoid_t(ar1);
            float c1 = tanh_ap(ph[q0 + 1] + r1 * ah1);
            float hn1 = c1 + z1 * (ho1 - c1);

            float z2 = sigmoid_t(az2v);
            float r2 = sigmoid_t(ar2v);
            float c2 = tanh_ap(ph[q0 + 2] + r2 * ah2v);
            float hn2 = c2 + z2 * (ho2 - c2);

            float z3 = sigmoid_t(az3);
            float r3 = sigmoid_t(ar3);
            float c3 = tanh_ap(ph[q0 + 3] + r3 * ah3);
            float hn3 = c3 + z3 * (ho3 - c3);

            sts_v2(ea, pack2(hn0, hn1), pack2(hn2, hn3));

            atomicAdd(g_m + slk[(q0    ) * 8 + s] * 32 + lane, hn0);
            atomicAdd(g_m + slk[(q0 + 1) * 8 + s] * 32 + lane, hn1);
            atomicAdd(g_m + slk[(q0 + 2) * 8 + s] * 32 + lane, hn2);
            atomicAdd(g_m + slk[(q0 + 3) * 8 + s] * 32 + lane, hn3);
        }
        __syncwarp();
    }

    // writeback h tile (coalesced per path)
    #pragma unroll 1
    for (int i = 0; i < PPW; i++)
        g_path_state[(pw + i) * 32 + lane] =
            shwf[lane * 20 + ((((unsigned)i >> 2) * 4u) ^ (sl16 >> 2)) + (i & 3)];
}

// ---------------- link phase (R9 form): warp per link, lane=dim -------------
__global__ void __launch_bounds__(256)
k_link(const float* __restrict__ Wl, const float* __restrict__ Ul,
       const float* __restrict__ bl, const float* __restrict__ Wp,
       const float* __restrict__ bp) {
    __shared__ float sWl[3072], sUl[3072], sWp[3072];
    __shared__ float sbl[192], sbp[192];
    const int tid = threadIdx.x;
    for (int i = tid; i < 3072; i += 256) { sWl[i] = Wl[i]; sUl[i] = Ul[i]; sWp[i] = Wp[i]; }
    if (tid < 192) { sbl[tid] = bl[tid]; sbp[tid] = bp[tid]; }
    __syncthreads();

    const int lane = tid & 31;
    const int L = blockIdx.x * 8 + (tid >> 5);        // 1250 * 8 = 10000 exact

    float mown = g_m[L * 32 + lane];
    float hown = g_link_state[L * 32 + lane];

    float az  = sbl[lane]      + sbl[96 + lane];
    float arx = sbl[32 + lane] + sbl[128 + lane];
    float axh = sbl[64 + lane];
    float ahh = sbl[160 + lane];

    #pragma unroll 1
    for (int k = 0; k < 32; k++) {
        float mk = __shfl_sync(0xffffffffu, mown, k);
        float hk = __shfl_sync(0xffffffffu, hown, k);
        const float* wl = sWl + k * 96 + lane;
        const float* ul = sUl + k * 96 + lane;
        az  = fmaf(mk, wl[0],  fmaf(hk, ul[0],  az));
        arx = fmaf(mk, wl[32], fmaf(hk, ul[32], arx));
        axh = fmaf(mk, wl[64], axh);
        ahh = fmaf(hk, ul[64], ahh);
    }

    float z  = sigmoid_t(az);
    float r  = sigmoid_t(arx);
    float c  = tanh_ap(axh + r * ahh);
    float hn = c + z * (hown - c);

    g_link_state[L * 32 + lane] = hn;
    g_m[L * 32 + lane] = 0.0f;                        // reset for next iteration

    // recompute LG = new_link_state @ Wp + biases, interleaved per-lane float4
    float l0 = sbp[lane]      + sbp[96 + lane];
    float l1 = sbp[32 + lane] + sbp[128 + lane];
    float l2 = sbp[64 + lane];
    #pragma unroll 1
    for (int k = 0; k < 32; k++) {
        float hk = __shfl_sync(0xffffffffu, hn, k);
        const float* wp = sWp + k * 96 + lane;
        l0 = fmaf(hk, wp[0],  l0);
        l1 = fmaf(hk, wp[32], l1);
        l2 = fmaf(hk, wp[64], l2);
    }
    reinterpret_cast<float4*>(g_LG)[L * 32 + lane] = make_float4(l0, l1, l2, 0.0f);
}

// ---------------- readout: lane-contiguous columns + f32x2 ------------------
__global__ void __launch_bounds__(128)
k_readout(const float* __restrict__ D1, const float* __restrict__ b1,
          const float* __restrict__ D2, const float* __restrict__ b2,
          const float* __restrict__ Wf, const float* __restrict__ bf,
          float* __restrict__ out) {
    __shared__ float sx1[4 * 8 * 256];   // per-warp [path][k] hidden1
    const int tid = threadIdx.x;
    const int lane = tid & 31, warp = tid >> 5;
    const int pbase = blockIdx.x * 32 + warp * 8;   // 100000 % 32 == 0
    float* myx1 = sx1 + warp * 2048;
    const int cb = 8 * lane;             // this lane's contiguous column base

    u64 bb1[4], bb2[4];
    ldg_v2(b1 + cb, bb1[0], bb1[1]);  ldg_v2(b1 + cb + 4, bb1[2], bb1[3]);
    ldg_v2(b2 + cb, bb2[0], bb2[1]);  ldg_v2(b2 + cb + 4, bb2[2], bb2[3]);

    float hsave[8];

    // ---- layer 1: 32 -> 256 + selu ----
    #pragma unroll 1
    for (int p = 0; p < 8; p++) {
        float hown = g_path_state[(pbase + p) * 32 + lane];
        hsave[p] = hown;
        u64 acc[4];
        #pragma unroll
        for (int i = 0; i < 4; i++) acc[i] = bb1[i];
        #pragma unroll 1
        for (int k = 0; k < 32; k++) {
            float hk = __shfl_sync(0xffffffffu, hown, k);
            u64 h2 = splat2(hk);
            const float* d1 = D1 + k * 256 + cb;
            u64 w0, w1, w2, w3;
            ldg_v2(d1, w0, w1); ldg_v2(d1 + 4, w2, w3);
            ffma2(acc[0], h2, w0); ffma2(acc[1], h2, w1);
            ffma2(acc[2], h2, w2); ffma2(acc[3], h2, w3);
        }
        float2* dst = reinterpret_cast<float2*>(myx1 + p * 256 + cb);
        #pragma unroll
        for (int i = 0; i < 4; i++) {
            float x0, x1; unpack2(acc[i], x0, x1);
            dst[i] = make_float2(seluf_(x0), seluf_(x1));
        }
    }
    __syncwarp();

    // ---- layer 2: 256 -> 256, f32x2, D2-row reuse across 8 paths ----
    u64 a2p[32];
    #pragma unroll
    for (int p = 0; p < 8; p++)
        #pragma unroll
        for (int i = 0; i < 4; i++) a2p[p * 4 + i] = bb2[i];

    #pragma unroll 1
    for (int k = 0; k < 256; k++) {
        const float* d2 = D2 + k * 256 + cb;
        u64 w0, w1, w2, w3;
        ldg_v2(d2, w0, w1); ldg_v2(d2 + 4, w2, w3);
        #pragma unroll
        for (int p = 0; p < 8; p++) {
            u64 x2 = splat2(myx1[p * 256 + k]);
            ffma2(a2p[p*4+0], x2, w0); ffma2(a2p[p*4+1], x2, w1);
            ffma2(a2p[p*4+2], x2, w2); ffma2(a2p[p*4+3], x2, w3);
        }
    }

    // ---- selu + final dense on concat(x2, h) ----
    const float2* Wf2 = reinterpret_cast<const float2*>(Wf);
    float2 wfx[8];
    #pragma unroll
    for (int i = 0; i < 8; i++) wfx[i] = __ldg(Wf2 + cb + i);
    float2 wfh = __ldg(Wf2 + 256 + lane);
    float bf0 = __ldg(bf), bf1 = __ldg(bf + 1);

    #pragma unroll 1
    for (int p = 0; p < 8; p++) {
        float hv = hsave[p];
        float s0 = hv * wfh.x, s1 = hv * wfh.y;
        #pragma unroll
        for (int i = 0; i < 4; i++) {
            float x0, x1; unpack2(a2p[p * 4 + i], x0, x1);
            x0 = seluf_(x0); x1 = seluf_(x1);
            s0 = fmaf(x0, wfx[2*i].x, fmaf(x1, wfx[2*i+1].x, s0));
            s1 = fmaf(x0, wfx[2*i].y, fmaf(x1, wfx[2*i+1].y, s1));
        }
        #pragma unroll
        for (int off = 16; off; off >>= 1) {
            s0 += __shfl_xor_sync(0xffffffffu, s0, off);
            s1 += __shfl_xor_sync(0xffffffffu, s1, off);
        }
        if (lane == 0)
            reinterpret_cast<float2*>(out)[pbase + p] = make_float2(s0 + bf0, s1 + bf1);
    }
}

// ---------------- launch ----------------
extern "C" void kernel_launch(void* const* d_in, const int* in_sizes, int n_in,
                              void* d_out, int out_size) {
    const float* cap     = (const float*)d_in[0];
    const float* traffic = (const float*)d_in[1];
    const int*   links   = (const int*)  d_in[2];
    const float* Wp = (const float*)d_in[5];
    const float* Up = (const float*)d_in[6];
    const float* bp = (const float*)d_in[7];
    const float* Wl = (const float*)d_in[8];
    const float* Ul = (const float*)d_in[9];
    const float* bl = (const float*)d_in[10];
    const float* D1 = (const float*)d_in[11];
    const float* b1 = (const float*)d_in[12];
    const float* D2 = (const float*)d_in[13];
    const float* b2 = (const float*)d_in[14];
    const float* Wf = (const float*)d_in[15];
    const float* bf = (const float*)d_in[16];
    float* out = (float*)d_out;

    k_init<<<(NPATHS * 32 + 255) / 256, 256>>>(cap, traffic, Wp, bp);
    for (int t = 0; t < 8; t++) {
        k_path<<<(NPATHS + 63) / 64, 128>>>(links, Up, bp);
        k_link<<<NLINKS / 8, 256>>>(Wl, Ul, bl, Wp, bp);
    }
    k_readout<<<NPATHS / 32, 128>>>(D1, b1, D2, b2, Wf, bf, out);
}

// round 12
// speedup vs baseline: 1.1046x; 1.1046x over previous
#include <cuda_runtime.h>

#define NPATHS 100000
#define NLINKS 10000

// ---------------- persistent device state ----------------
__device__ __align__(16) float g_link_state[NLINKS * 32];
__device__ __align__(16) float g_path_state[NPATHS * 32];
__device__ __align__(16) float g_m[NLINKS * 32];          // segment sums
__device__ __align__(16) float g_LG[NLINKS * 96];         // link_state @ Wp + biases

// ---------------- packed f32x2 helpers ----------------
typedef unsigned long long u64;

__device__ __forceinline__ u64 splat2(float x) {
    u64 r; asm("mov.b64 %0, {%1, %1};" : "=l"(r) : "f"(x)); return r;
}
__device__ __forceinline__ u64 pack2(float a, float b) {
    u64 r; asm("mov.b64 %0, {%1, %2};" : "=l"(r) : "f"(a), "f"(b)); return r;
}
__device__ __forceinline__ void unpack2(u64 v, float& a, float& b) {
    asm("mov.b64 {%0, %1}, %2;" : "=f"(a), "=f"(b) : "l"(v));
}
__device__ __forceinline__ void ffma2(u64& d, u64 a, u64 b) {
    asm("fma.rn.f32x2 %0, %1, %2, %0;" : "+l"(d) : "l"(a), "l"(b));
}
__device__ __forceinline__ void lds_v2(unsigned addr, u64& a, u64& b) {
    asm volatile("ld.shared.v2.u64 {%0, %1}, [%2];" : "=l"(a), "=l"(b) : "r"(addr));
}
__device__ __forceinline__ void sts_v2(unsigned addr, u64 a, u64 b) {
    asm volatile("st.shared.v2.u64 [%0], {%1, %2};" :: "r"(addr), "l"(a), "l"(b) : "memory");
}
__device__ __forceinline__ void ldg_v2(const void* p, u64& a, u64& b) {
    asm volatile("ld.global.nc.v2.u64 {%0, %1}, [%2];" : "=l"(a), "=l"(b) : "l"(p));
}

// ---------------- fast activations ----------------
__device__ __forceinline__ float tanh_ap(float x) {
    float r; asm("tanh.approx.f32 %0, %1;" : "=f"(r) : "f"(x)); return r;
}
__device__ __forceinline__ float sigmoid_t(float x) {
    return fmaf(tanh_ap(0.5f * x), 0.5f, 0.5f);
}
__device__ __forceinline__ float seluf_(float x) {
    const float sc = 1.0507009873554805f;
    const float al = 1.6732632423543772f;
    return x > 0.0f ? sc * x : sc * al * (__expf(x) - 1.0f);
}

// ---------------- init: states, m=0, initial LG ----------------
__global__ void k_init(const float* __restrict__ cap, const float* __restrict__ traffic,
                       const float* __restrict__ Wp, const float* __restrict__ bp) {
    int idx = blockIdx.x * blockDim.x + threadIdx.x;
    if (idx < NPATHS * 32)
        g_path_state[idx] = ((idx & 31) == 0) ? traffic[idx >> 5] : 0.0f;
    if (idx < NLINKS * 32) {
        g_link_state[idx] = ((idx & 31) == 0) ? cap[idx >> 5] : 0.0f;
        g_m[idx] = 0.0f;
    }
    if (idx < NLINKS * 96) {
        int l = idx / 96;
        int j = idx - l * 96;
        float v = cap[l] * Wp[j] + bp[j];        // input bias bp[0]
        if (j < 64) v += bp[96 + j];             // fold recurrent bias bp[1] for z,r
        g_LG[idx] = v;
    }
}

// ---------------- path phase v7b: lane=dim, warp=16 paths -------------------
// z/r gather folded into acc init after batch-issuing all loads; ph prefetched;
// 5 blocks/SM; k-loop unroll 4.
#define PPW 16          // paths per warp
#define NPAIR 8         // path pairs per warp
#define HSTRB 80u       // bytes per dim row (10 u64: 4 groups x 16B + 16B pad)

__global__ void __launch_bounds__(128, 5)
k_path(const int* __restrict__ links, const float* __restrict__ Up,
       const float* __restrict__ bp) {
    __shared__ __align__(16) float sUp[3072];            // Up [k][j] row-major f32
    __shared__ int slinks[64 * 8];                       // 64 paths per block
    __shared__ __align__(16) char shtile[4 * 32 * HSTRB];// per warp: h[dim][group swz]

    const int tid  = threadIdx.x;
    const int lane = tid & 31;
    const int warp = tid >> 5;
    const int p0   = blockIdx.x * 64;                    // 64 paths per block

    for (int i = tid; i < 3072; i += 128) sUp[i] = Up[i];
    for (int i = tid; i < 512; i += 128) {
        int e = p0 * 8 + i;
        slinks[i] = (e < NPATHS * 8) ? links[e] : 0;
    }
    __syncthreads();

    const int pw = p0 + warp * PPW;
    if (pw >= NPATHS) return;                            // whole-warp exit

    char* shw = shtile + warp * 32 * HSTRB;
    float* shwf = reinterpret_cast<float*>(shw);
    const unsigned shw_a = (unsigned)__cvta_generic_to_shared(shw);
    const unsigned sl16 = ((unsigned)(lane >> 3) & 3u) * 16u;   // owner-dim swizzle (bytes)

    // initial h load: float slot = lane*20 + (((i>>2)*4) ^ (sl16>>2)) + (i&3)
    #pragma unroll 1
    for (int i = 0; i < PPW; i++)
        shwf[lane * 20 + ((((unsigned)i >> 2) * 4u) ^ (sl16 >> 2)) + (i & 3)] =
            g_path_state[(pw + i) * 32 + lane];
    __syncwarp();

    const u64 b1h2 = splat2(__ldg(bp + 96 + 64 + lane));
    const int* slk = slinks + warp * PPW * 8;

    #pragma unroll 1
    for (int s = 0; s < 8; s++) {
        // prologue: issue ALL LG gather loads, then fold z/r into acc init.
        float pz[PPW], pr[PPW], ph[PPW];
        #pragma unroll
        for (int q = 0; q < PPW; q++) {
            const float* lg = g_LG + slk[q * 8 + s] * 96 + lane;
            pz[q] = __ldg(lg);
            pr[q] = __ldg(lg + 32);
            ph[q] = __ldg(lg + 64);
        }

        u64 accz[NPAIR], accr[NPAIR], acch[NPAIR];
        #pragma unroll
        for (int p2 = 0; p2 < NPAIR; p2++) {
            accz[p2] = pack2(pz[2 * p2], pz[2 * p2 + 1]);
            accr[p2] = pack2(pr[2 * p2], pr[2 * p2 + 1]);
            acch[p2] = b1h2;
        }

        // recurrent matvec: acc += h @ Up
        #pragma unroll 4
        for (int k = 0; k < 32; k++) {
            const float* w = sUp + k * 96 + lane;
            u64 wz2 = splat2(w[0]);
            u64 wr2 = splat2(w[32]);
            u64 wh2 = splat2(w[64]);
            unsigned ha = shw_a + (unsigned)k * HSTRB;
            unsigned sk16 = ((unsigned)(k >> 3) & 3u) * 16u;
            #pragma unroll
            for (int g = 0; g < 4; g++) {
                u64 hA, hB;
                lds_v2(ha + (((unsigned)g * 16u) ^ sk16), hA, hB);
                ffma2(accz[2*g],   hA, wz2);
                ffma2(accz[2*g+1], hB, wz2);
                ffma2(accr[2*g],   hA, wr2);
                ffma2(accr[2*g+1], hB, wr2);
                ffma2(acch[2*g],   hA, wh2);
                ffma2(acch[2*g+1], hB, wh2);
            }
        }

        // epilogue: gates, state update, coalesced scatter
        #pragma unroll
        for (int g = 0; g < 4; g++) {
            const int q0 = 4 * g;
            unsigned ea = shw_a + (unsigned)lane * HSTRB + (((unsigned)g * 16u) ^ sl16);
            u64 hoA2, hoB2;
            lds_v2(ea, hoA2, hoB2);
            float ho0, ho1, ho2, ho3;
            unpack2(hoA2, ho0, ho1);
            unpack2(hoB2, ho2, ho3);

            float az0, az1, az2v, az3, ar0, ar1, ar2v, ar3, ah0, ah1, ah2v, ah3;
            unpack2(accz[2*g], az0, az1);   unpack2(accz[2*g+1], az2v, az3);
            unpack2(accr[2*g], ar0, ar1);   unpack2(accr[2*g+1], ar2v, ar3);
            unpack2(acch[2*g], ah0, ah1);   unpack2(acch[2*g+1], ah2v, ah3);

            float z0 = sigmoid_t(az0);
            float r0 = sigmoid_t(ar0);
            float c0 = tanh_ap(ph[q0] + r0 * ah0);
            float hn0 = c0 + z0 * (ho0 - c0);

            float z1 = sigmoid_t(az1);
            float r1 = sigmoid_t(ar1);
            float c1 = tanh_ap(ph[q0 + 1] + r1 * ah1);
            float hn1 = c1 + z1 * (ho1 - c1);

            float z2 = sigmoid_t(az2v);
            float r2 = sigmoid_t(ar2v);
            float c2 = tanh_ap(ph[q0 + 2] + r2 * ah2v);
            float hn2 = c2 + z2 * (ho2 - c2);

            float z3 = sigmoid_t(az3);
            float r3 = sigmoid_t(ar3);
            float c3 = tanh_ap(ph[q0 + 3] + r3 * ah3);
            float hn3 = c3 + z3 * (ho3 - c3);

            sts_v2(ea, pack2(hn0, hn1), pack2(hn2, hn3));

            atomicAdd(g_m + slk[(q0    ) * 8 + s] * 32 + lane, hn0);
            atomicAdd(g_m + slk[(q0 + 1) * 8 + s] * 32 + lane, hn1);
            atomicAdd(g_m + slk[(q0 + 2) * 8 + s] * 32 + lane, hn2);
            atomicAdd(g_m + slk[(q0 + 3) * 8 + s] * 32 + lane, hn3);
        }
        __syncwarp();
    }

    // writeback h tile (coalesced per path)
    #pragma unroll 1
    for (int i = 0; i < PPW; i++)
        g_path_state[(pw + i) * 32 + lane] =
            shwf[lane * 20 + ((((unsigned)i >> 2) * 4u) ^ (sl16 >> 2)) + (i & 3)];
}

// ---------------- link phase (R9 form): warp per link, lane=dim -------------
__global__ void __launch_bounds__(256)
k_link(const float* __restrict__ Wl, const float* __restrict__ Ul,
       const float* __restrict__ bl, const float* __restrict__ Wp,
       const float* __restrict__ bp) {
    __shared__ float sWl[3072], sUl[3072], sWp[3072];
    __shared__ float sbl[192], sbp[192];
    const int tid = threadIdx.x;
    for (int i = tid; i < 3072; i += 256) { sWl[i] = Wl[i]; sUl[i] = Ul[i]; sWp[i] = Wp[i]; }
    if (tid < 192) { sbl[tid] = bl[tid]; sbp[tid] = bp[tid]; }
    __syncthreads();

    const int lane = tid & 31;
    const int L = blockIdx.x * 8 + (tid >> 5);        // 1250 * 8 = 10000 exact

    float mown = g_m[L * 32 + lane];
    float hown = g_link_state[L * 32 + lane];

    float az  = sbl[lane]      + sbl[96 + lane];
    float arx = sbl[32 + lane] + sbl[128 + lane];
    float axh = sbl[64 + lane];
    float ahh = sbl[160 + lane];

    #pragma unroll 1
    for (int k = 0; k < 32; k++) {
        float mk = __shfl_sync(0xffffffffu, mown, k);
        float hk = __shfl_sync(0xffffffffu, hown, k);
        const float* wl = sWl + k * 96 + lane;
        const float* ul = sUl + k * 96 + lane;
        az  = fmaf(mk, wl[0],  fmaf(hk, ul[0],  az));
        arx = fmaf(mk, wl[32], fmaf(hk, ul[32], arx));
        axh = fmaf(mk, wl[64], axh);
        ahh = fmaf(hk, ul[64], ahh);
    }

    float z  = sigmoid_t(az);
    float r  = sigmoid_t(arx);
    float c  = tanh_ap(axh + r * ahh);
    float hn = c + z * (hown - c);

    g_link_state[L * 32 + lane] = hn;
    g_m[L * 32 + lane] = 0.0f;                        // reset for next iteration

    // recompute LG = new_link_state @ Wp + biases (lane owns cols j, 32+j, 64+j)
    float l0 = sbp[lane]      + sbp[96 + lane];
    float l1 = sbp[32 + lane] + sbp[128 + lane];
    float l2 = sbp[64 + lane];
    #pragma unroll 1
    for (int k = 0; k < 32; k++) {
        float hk = __shfl_sync(0xffffffffu, hn, k);
        const float* wp = sWp + k * 96 + lane;
        l0 = fmaf(hk, wp[0],  l0);
        l1 = fmaf(hk, wp[32], l1);
        l2 = fmaf(hk, wp[64], l2);
    }
    g_LG[L * 96 + lane]      = l0;
    g_LG[L * 96 + 32 + lane] = l1;
    g_LG[L * 96 + 64 + lane] = l2;
}

// ---------------- readout: lane-contiguous columns + f32x2 ------------------
__global__ void __launch_bounds__(128)
k_readout(const float* __restrict__ D1, const float* __restrict__ b1,
          const float* __restrict__ D2, const float* __restrict__ b2,
          const float* __restrict__ Wf, const float* __restrict__ bf,
          float* __restrict__ out) {
    __shared__ float sx1[4 * 8 * 256];   // per-warp [path][k] hidden1
    const int tid = threadIdx.x;
    const int lane = tid & 31, warp = tid >> 5;
    const int pbase = blockIdx.x * 32 + warp * 8;   // 100000 % 32 == 0
    float* myx1 = sx1 + warp * 2048;
    const int cb = 8 * lane;             // this lane's contiguous column base

    u64 bb1[4], bb2[4];
    ldg_v2(b1 + cb, bb1[0], bb1[1]);  ldg_v2(b1 + cb + 4, bb1[2], bb1[3]);
    ldg_v2(b2 + cb, bb2[0], bb2[1]);  ldg_v2(b2 + cb + 4, bb2[2], bb2[3]);

    float hsave[8];

    // ---- layer 1: 32 -> 256 + selu ----
    #pragma unroll 1
    for (int p = 0; p < 8; p++) {
        float hown = g_path_state[(pbase + p) * 32 + lane];
        hsave[p] = hown;
        u64 acc[4];
        #pragma unroll
        for (int i = 0; i < 4; i++) acc[i] = bb1[i];
        #pragma unroll 1
        for (int k = 0; k < 32; k++) {
            float hk = __shfl_sync(0xffffffffu, hown, k);
            u64 h2 = splat2(hk);
            const float* d1 = D1 + k * 256 + cb;
            u64 w0, w1, w2, w3;
            ldg_v2(d1, w0, w1); ldg_v2(d1 + 4, w2, w3);
            ffma2(acc[0], h2, w0); ffma2(acc[1], h2, w1);
            ffma2(acc[2], h2, w2); ffma2(acc[3], h2, w3);
        }
        float2* dst = reinterpret_cast<float2*>(myx1 + p * 256 + cb);
        #pragma unroll
        for (int i = 0; i < 4; i++) {
            float x0, x1; unpack2(acc[i], x0, x1);
            dst[i] = make_float2(seluf_(x0), seluf_(x1));
        }
    }
    __syncwarp();

    // ---- layer 2: 256 -> 256, f32x2, D2-row reuse across 8 paths ----
    u64 a2p[32];
    #pragma unroll
    for (int p = 0; p < 8; p++)
        #pragma unroll
        for (int i = 0; i < 4; i++) a2p[p * 4 + i] = bb2[i];

    #pragma unroll 1
    for (int k = 0; k < 256; k++) {
        const float* d2 = D2 + k * 256 + cb;
        u64 w0, w1, w2, w3;
        ldg_v2(d2, w0, w1); ldg_v2(d2 + 4, w2, w3);
        #pragma unroll
        for (int p = 0; p < 8; p++) {
            u64 x2 = splat2(myx1[p * 256 + k]);
            ffma2(a2p[p*4+0], x2, w0); ffma2(a2p[p*4+1], x2, w1);
            ffma2(a2p[p*4+2], x2, w2); ffma2(a2p[p*4+3], x2, w3);
        }
    }

    // ---- selu + final dense on concat(x2, h) ----
    const float2* Wf2 = reinterpret_cast<const float2*>(Wf);
    float2 wfx[8];
    #pragma unroll
    for (int i = 0; i < 8; i++) wfx[i] = __ldg(Wf2 + cb + i);
    float2 wfh = __ldg(Wf2 + 256 + lane);
    float bf0 = __ldg(bf), bf1 = __ldg(bf + 1);

    #pragma unroll 1
    for (int p = 0; p < 8; p++) {
        float hv = hsave[p];
        float s0 = hv * wfh.x, s1 = hv * wfh.y;
        #pragma unroll
        for (int i = 0; i < 4; i++) {
            float x0, x1; unpack2(a2p[p * 4 + i], x0, x1);
            x0 = seluf_(x0); x1 = seluf_(x1);
            s0 = fmaf(x0, wfx[2*i].x, fmaf(x1, wfx[2*i+1].x, s0));
            s1 = fmaf(x0, wfx[2*i].y, fmaf(x1, wfx[2*i+1].y, s1));
        }
        #pragma unroll
        for (int off = 16; off; off >>= 1) {
            s0 += __shfl_xor_sync(0xffffffffu, s0, off);
            s1 += __shfl_xor_sync(0xffffffffu, s1, off);
        }
        if (lane == 0)
            reinterpret_cast<float2*>(out)[pbase + p] = make_float2(s0 + bf0, s1 + bf1);
    }
}

// ---------------- launch ----------------
extern "C" void kernel_launch(void* const* d_in, const int* in_sizes, int n_in,
                              void* d_out, int out_size) {
    const float* cap     = (const float*)d_in[0];
    const float* traffic = (const float*)d_in[1];
    const int*   links   = (const int*)  d_in[2];
    const float* Wp = (const float*)d_in[5];
    const float* Up = (const float*)d_in[6];
    const float* bp = (const float*)d_in[7];
    const float* Wl = (const float*)d_in[8];
    const float* Ul = (const float*)d_in[9];
    const float* bl = (const float*)d_in[10];
    const float* D1 = (const float*)d_in[11];
    const float* b1 = (const float*)d_in[12];
    const float* D2 = (const float*)d_in[13];
    const float* b2 = (const float*)d_in[14];
    const float* Wf = (const float*)d_in[15];
    const float* bf = (const float*)d_in[16];
    float* out = (float*)d_out;

    k_init<<<(NPATHS * 32 + 255) / 256, 256>>>(cap, traffic, Wp, bp);
    for (int t = 0; t < 8; t++) {
        k_path<<<(NPATHS + 63) / 64, 128>>>(links, Up, bp);
        k_link<<<NLINKS / 8, 256>>>(Wl, Ul, bl, Wp, bp);
    }
    k_readout<<<NPATHS / 32, 128>>>(D1, b1, D2, b2, Wf, bf, out);
}

// round 14
// speedup vs baseline: 1.1069x; 1.0021x over previous
#include <cuda_runtime.h>

#define NPATHS 100000
#define NLINKS 10000

// ---------------- persistent device state ----------------
__device__ __align__(16) float g_link_state[NLINKS * 32];
__device__ __align__(16) float g_path_state[NPATHS * 32];
__device__ __align__(16) float g_m[NLINKS * 32];          // segment sums
__device__ __align__(16) float g_LG[NLINKS * 96];         // link_state @ Wp + biases

// ---------------- packed f32x2 helpers ----------------
typedef unsigned long long u64;

__device__ __forceinline__ u64 splat2(float x) {
    u64 r; asm("mov.b64 %0, {%1, %1};" : "=l"(r) : "f"(x)); return r;
}
__device__ __forceinline__ u64 pack2(float a, float b) {
    u64 r; asm("mov.b64 %0, {%1, %2};" : "=l"(r) : "f"(a), "f"(b)); return r;
}
__device__ __forceinline__ void unpack2(u64 v, float& a, float& b) {
    asm("mov.b64 {%0, %1}, %2;" : "=f"(a), "=f"(b) : "l"(v));
}
__device__ __forceinline__ void ffma2(u64& d, u64 a, u64 b) {
    asm("fma.rn.f32x2 %0, %1, %2, %0;" : "+l"(d) : "l"(a), "l"(b));
}
__device__ __forceinline__ void lds_v2(unsigned addr, u64& a, u64& b) {
    asm volatile("ld.shared.v2.u64 {%0, %1}, [%2];" : "=l"(a), "=l"(b) : "r"(addr));
}
__device__ __forceinline__ void sts_v2(unsigned addr, u64 a, u64 b) {
    asm volatile("st.shared.v2.u64 [%0], {%1, %2};" :: "r"(addr), "l"(a), "l"(b) : "memory");
}
__device__ __forceinline__ void ldg_v2(const void* p, u64& a, u64& b) {
    asm volatile("ld.global.nc.v2.u64 {%0, %1}, [%2];" : "=l"(a), "=l"(b) : "l"(p));
}

// ---------------- fast activations ----------------
__device__ __forceinline__ float tanh_ap(float x) {
    float r; asm("tanh.approx.f32 %0, %1;" : "=f"(r) : "f"(x)); return r;
}
__device__ __forceinline__ float sigmoid_t(float x) {
    return fmaf(tanh_ap(0.5f * x), 0.5f, 0.5f);
}
__device__ __forceinline__ float seluf_(float x) {
    const float sc = 1.0507009873554805f;
    const float al = 1.6732632423543772f;
    return x > 0.0f ? sc * x : sc * al * (__expf(x) - 1.0f);
}

// ---------------- init (links only): link_state, m=0, initial LG ------------
__global__ void k_init(const float* __restrict__ cap,
                       const float* __restrict__ Wp, const float* __restrict__ bp) {
    int idx = blockIdx.x * blockDim.x + threadIdx.x;
    if (idx < NLINKS * 32) {
        g_link_state[idx] = ((idx & 31) == 0) ? cap[idx >> 5] : 0.0f;
        g_m[idx] = 0.0f;
    }
    if (idx < NLINKS * 96) {
        int l = idx / 96;
        int j = idx - l * 96;
        float v = cap[l] * Wp[j] + bp[j];        // input bias bp[0]
        if (j < 64) v += bp[96 + j];             // fold recurrent bias bp[1] for z,r
        g_LG[idx] = v;
    }
}

// ---------------- path phase v9: lane=dim, warp=16 paths --------------------
// FIRST: h synthesized from traffic (no path_state read).
// LAST:  segment-sum atomics skipped (m unused afterwards).
#define PPW 16          // paths per warp
#define NPAIR 8         // path pairs per warp
#define HSTRB 80u       // bytes per dim row (10 u64: 4 groups x 16B + 16B pad)

template <bool FIRST, bool LAST>
__global__ void __launch_bounds__(128, 5)
k_path(const int* __restrict__ links, const float* __restrict__ Up,
       const float* __restrict__ bp, const float* __restrict__ traffic) {
    __shared__ __align__(16) float sUp[3072];            // Up [k][j] row-major f32
    __shared__ int slinks[64 * 8];                       // 64 paths per block
    __shared__ __align__(16) char shtile[4 * 32 * HSTRB];// per warp: h[dim][group swz]

    const int tid  = threadIdx.x;
    const int lane = tid & 31;
    const int warp = tid >> 5;
    const int p0   = blockIdx.x * 64;                    // 64 paths per block

    for (int i = tid; i < 3072; i += 128) sUp[i] = Up[i];
    for (int i = tid; i < 512; i += 128) {
        int e = p0 * 8 + i;
        slinks[i] = (e < NPATHS * 8) ? links[e] : 0;
    }
    __syncthreads();

    const int pw = p0 + warp * PPW;
    if (pw >= NPATHS) return;                            // whole-warp exit

    char* shw = shtile + warp * 32 * HSTRB;
    float* shwf = reinterpret_cast<float*>(shw);
    const unsigned shw_a = (unsigned)__cvta_generic_to_shared(shw);
    const unsigned sl16 = ((unsigned)(lane >> 3) & 3u) * 16u;   // owner-dim swizzle (bytes)

    // initial h: float slot = lane*20 + (((i>>2)*4) ^ (sl16>>2)) + (i&3)
    #pragma unroll 1
    for (int i = 0; i < PPW; i++) {
        float v;
        if (FIRST) {
            v = (lane == 0) ? __ldg(traffic + pw + i) : 0.0f;
        } else {
            v = g_path_state[(pw + i) * 32 + lane];
        }
        shwf[lane * 20 + ((((unsigned)i >> 2) * 4u) ^ (sl16 >> 2)) + (i & 3)] = v;
    }
    __syncwarp();

    const u64 b1h2 = splat2(__ldg(bp + 96 + 64 + lane));
    const int* slk = slinks + warp * PPW * 8;

    #pragma unroll 1
    for (int s = 0; s < 8; s++) {
        // prologue: issue ALL LG gather loads, then fold z/r into acc init.
        float pz[PPW], pr[PPW], ph[PPW];
        #pragma unroll
        for (int q = 0; q < PPW; q++) {
            const float* lg = g_LG + slk[q * 8 + s] * 96 + lane;
            pz[q] = __ldg(lg);
            pr[q] = __ldg(lg + 32);
            ph[q] = __ldg(lg + 64);
        }

        u64 accz[NPAIR], accr[NPAIR], acch[NPAIR];
        #pragma unroll
        for (int p2 = 0; p2 < NPAIR; p2++) {
            accz[p2] = pack2(pz[2 * p2], pz[2 * p2 + 1]);
            accr[p2] = pack2(pr[2 * p2], pr[2 * p2 + 1]);
            acch[p2] = b1h2;
        }

        // recurrent matvec: acc += h @ Up
        #pragma unroll 2
        for (int k = 0; k < 32; k++) {
            const float* w = sUp + k * 96 + lane;
            u64 wz2 = splat2(w[0]);
            u64 wr2 = splat2(w[32]);
            u64 wh2 = splat2(w[64]);
            unsigned ha = shw_a + (unsigned)k * HSTRB;
            unsigned sk16 = ((unsigned)(k >> 3) & 3u) * 16u;
            #pragma unroll
            for (int g = 0; g < 4; g++) {
                u64 hA, hB;
                lds_v2(ha + (((unsigned)g * 16u) ^ sk16), hA, hB);
                ffma2(accz[2*g],   hA, wz2);
                ffma2(accz[2*g+1], hB, wz2);
                ffma2(accr[2*g],   hA, wr2);
                ffma2(accr[2*g+1], hB, wr2);
                ffma2(acch[2*g],   hA, wh2);
                ffma2(acch[2*g+1], hB, wh2);
            }
        }

        // epilogue: gates, state update, (conditional) coalesced scatter
        #pragma unroll
        for (int g = 0; g < 4; g++) {
            const int q0 = 4 * g;
            unsigned ea = shw_a + (unsigned)lane * HSTRB + (((unsigned)g * 16u) ^ sl16);
            u64 hoA2, hoB2;
            lds_v2(ea, hoA2, hoB2);
            float ho0, ho1, ho2, ho3;
            unpack2(hoA2, ho0, ho1);
            unpack2(hoB2, ho2, ho3);

            float az0, az1, az2v, az3, ar0, ar1, ar2v, ar3, ah0, ah1, ah2v, ah3;
            unpack2(accz[2*g], az0, az1);   unpack2(accz[2*g+1], az2v, az3);
            unpack2(accr[2*g], ar0, ar1);   unpack2(accr[2*g+1], ar2v, ar3);
            unpack2(acch[2*g], ah0, ah1);   unpack2(acch[2*g+1], ah2v, ah3);

            float z0 = sigmoid_t(az0);
            float r0 = sigmoid_t(ar0);
            float c0 = tanh_ap(ph[q0] + r0 * ah0);
            float hn0 = c0 + z0 * (ho0 - c0);

            float z1 = sigmoid_t(az1);
            float r1 = sigmoid_t(ar1);
            float c1 = tanh_ap(ph[q0 + 1] + r1 * ah1);
            float hn1 = c1 + z1 * (ho1 - c1);

            float z2 = sigmoid_t(az2v);
            float r2 = sigmoid_t(ar2v);
            float c2 = tanh_ap(ph[q0 + 2] + r2 * ah2v);
            float hn2 = c2 + z2 * (ho2 - c2);

            float z3 = sigmoid_t(az3);
            float r3 = sigmoid_t(ar3);
            float c3 = tanh_ap(ph[q0 + 3] + r3 * ah3);
            float hn3 = c3 + z3 * (ho3 - c3);

            sts_v2(ea, pack2(hn0, hn1), pack2(hn2, hn3));

            if (!LAST) {
                atomicAdd(g_m + slk[(q0    ) * 8 + s] * 32 + lane, hn0);
                atomicAdd(g_m + slk[(q0 + 1) * 8 + s] * 32 + lane, hn1);
                atomicAdd(g_m + slk[(q0 + 2) * 8 + s] * 32 + lane, hn2);
                atomicAdd(g_m + slk[(q0 + 3) * 8 + s] * 32 + lane, hn3);
            }
        }
        __syncwarp();
    }

    // writeback h tile (coalesced per path)
    #pragma unroll 1
    for (int i = 0; i < PPW; i++)
        g_path_state[(pw + i) * 32 + lane] =
            shwf[lane * 20 + ((((unsigned)i >> 2) * 4u) ^ (sl16 >> 2)) + (i & 3)];
}

// ---------------- link phase: warp per link, lane=dim -----------------------
__global__ void __launch_bounds__(256)
k_link(const float* __restrict__ Wl, const float* __restrict__ Ul,
       const float* __restrict__ bl, const float* __restrict__ Wp,
       const float* __restrict__ bp) {
    __shared__ float sWl[3072], sUl[3072], sWp[3072];
    __shared__ float sbl[192], sbp[192];
    const int tid = threadIdx.x;
    for (int i = tid; i < 3072; i += 256) { sWl[i] = Wl[i]; sUl[i] = Ul[i]; sWp[i] = Wp[i]; }
    if (tid < 192) { sbl[tid] = bl[tid]; sbp[tid] = bp[tid]; }
    __syncthreads();

    const int lane = tid & 31;
    const int L = blockIdx.x * 8 + (tid >> 5);        // 1250 * 8 = 10000 exact

    float mown = g_m[L * 32 + lane];
    float hown = g_link_state[L * 32 + lane];

    float az  = sbl[lane]      + sbl[96 + lane];
    float arx = sbl[32 + lane] + sbl[128 + lane];
    float axh = sbl[64 + lane];
    float ahh = sbl[160 + lane];

    #pragma unroll 1
    for (int k = 0; k < 32; k++) {
        float mk = __shfl_sync(0xffffffffu, mown, k);
        float hk = __shfl_sync(0xffffffffu, hown, k);
        const float* wl = sWl + k * 96 + lane;
        const float* ul = sUl + k * 96 + lane;
        az  = fmaf(mk, wl[0],  fmaf(hk, ul[0],  az));
        arx = fmaf(mk, wl[32], fmaf(hk, ul[32], arx));
        axh = fmaf(mk, wl[64], axh);
        ahh = fmaf(hk, ul[64], ahh);
    }

    float z  = sigmoid_t(az);
    float r  = sigmoid_t(arx);
    float c  = tanh_ap(axh + r * ahh);
    float hn = c + z * (hown - c);

    g_link_state[L * 32 + lane] = hn;
    g_m[L * 32 + lane] = 0.0f;                        // reset for next iteration

    // recompute LG = new_link_state @ Wp + biases (lane owns cols j, 32+j, 64+j)
    float l0 = sbp[lane]      + sbp[96 + lane];
    float l1 = sbp[32 + lane] + sbp[128 + lane];
    float l2 = sbp[64 + lane];
    #pragma unroll 1
    for (int k = 0; k < 32; k++) {
        float hk = __shfl_sync(0xffffffffu, hn, k);
        const float* wp = sWp + k * 96 + lane;
        l0 = fmaf(hk, wp[0],  l0);
        l1 = fmaf(hk, wp[32], l1);
        l2 = fmaf(hk, wp[64], l2);
    }
    g_LG[L * 96 + lane]      = l0;
    g_LG[L * 96 + 32 + lane] = l1;
    g_LG[L * 96 + 64 + lane] = l2;
}

// ---------------- readout: lane-contiguous columns + f32x2 ------------------
__global__ void __launch_bounds__(128)
k_readout(const float* __restrict__ D1, const float* __restrict__ b1,
          const float* __restrict__ D2, const float* __restrict__ b2,
          const float* __restrict__ Wf, const float* __restrict__ bf,
          float* __restrict__ out) {
    __shared__ float sx1[4 * 8 * 256];   // per-warp [path][k] hidden1
    const int tid = threadIdx.x;
    const int lane = tid & 31, warp = tid >> 5;
    const int pbase = blockIdx.x * 32 + warp * 8;   // 100000 % 32 == 0
    float* myx1 = sx1 + warp * 2048;
    const int cb = 8 * lane;             // this lane's contiguous column base

    u64 bb1[4], bb2[4];
    ldg_v2(b1 + cb, bb1[0], bb1[1]);  ldg_v2(b1 + cb + 4, bb1[2], bb1[3]);
    ldg_v2(b2 + cb, bb2[0], bb2[1]);  ldg_v2(b2 + cb + 4, bb2[2], bb2[3]);

    float hsave[8];

    // ---- layer 1: 32 -> 256 + selu ----
    #pragma unroll 1
    for (int p = 0; p < 8; p++) {
        float hown = g_path_state[(pbase + p) * 32 + lane];
        hsave[p] = hown;
        u64 acc[4];
        #pragma unroll
        for (int i = 0; i < 4; i++) acc[i] = bb1[i];
        #pragma unroll 1
        for (int k = 0; k < 32; k++) {
            float hk = __shfl_sync(0xffffffffu, hown, k);
            u64 h2 = splat2(hk);
            const float* d1 = D1 + k * 256 + cb;
            u64 w0, w1, w2, w3;
            ldg_v2(d1, w0, w1); ldg_v2(d1 + 4, w2, w3);
            ffma2(acc[0], h2, w0); ffma2(acc[1], h2, w1);
            ffma2(acc[2], h2, w2); ffma2(acc[3], h2, w3);
        }
        float2* dst = reinterpret_cast<float2*>(myx1 + p * 256 + cb);
        #pragma unroll
        for (int i = 0; i < 4; i++) {
            float x0, x1; unpack2(acc[i], x0, x1);
            dst[i] = make_float2(seluf_(x0), seluf_(x1));
        }
    }
    __syncwarp();

    // ---- layer 2: 256 -> 256, f32x2, D2-row reuse across 8 paths ----
    u64 a2p[32];
    #pragma unroll
    for (int p = 0; p < 8; p++)
        #pragma unroll
        for (int i = 0; i < 4; i++) a2p[p * 4 + i] = bb2[i];

    #pragma unroll 1
    for (int k = 0; k < 256; k++) {
        const float* d2 = D2 + k * 256 + cb;
        u64 w0, w1, w2, w3;
        ldg_v2(d2, w0, w1); ldg_v2(d2 + 4, w2, w3);
        #pragma unroll
        for (int p = 0; p < 8; p++) {
            u64 x2 = splat2(myx1[p * 256 + k]);
            ffma2(a2p[p*4+0], x2, w0); ffma2(a2p[p*4+1], x2, w1);
            ffma2(a2p[p*4+2], x2, w2); ffma2(a2p[p*4+3], x2, w3);
        }
    }

    // ---- selu + final dense on concat(x2, h) ----
    const float2* Wf2 = reinterpret_cast<const float2*>(Wf);
    float2 wfx[8];
    #pragma unroll
    for (int i = 0; i < 8; i++) wfx[i] = __ldg(Wf2 + cb + i);
    float2 wfh = __ldg(Wf2 + 256 + lane);
    float bf0 = __ldg(bf), bf1 = __ldg(bf + 1);

    #pragma unroll 1
    for (int p = 0; p < 8; p++) {
        float hv = hsave[p];
        float s0 = hv * wfh.x, s1 = hv * wfh.y;
        #pragma unroll
        for (int i = 0; i < 4; i++) {
            float x0, x1; unpack2(a2p[p * 4 + i], x0, x1);
            x0 = seluf_(x0); x1 = seluf_(x1);
            s0 = fmaf(x0, wfx[2*i].x, fmaf(x1, wfx[2*i+1].x, s0));
            s1 = fmaf(x0, wfx[2*i].y, fmaf(x1, wfx[2*i+1].y, s1));
        }
        #pragma unroll
        for (int off = 16; off; off >>= 1) {
            s0 += __shfl_xor_sync(0xffffffffu, s0, off);
            s1 += __shfl_xor_sync(0xffffffffu, s1, off);
        }
        if (lane == 0)
            reinterpret_cast<float2*>(out)[pbase + p] = make_float2(s0 + bf0, s1 + bf1);
    }
}

// ---------------- launch ----------------
extern "C" void kernel_launch(void* const* d_in, const int* in_sizes, int n_in,
                              void* d_out, int out_size) {
    const float* cap     = (const float*)d_in[0];
    const float* traffic = (const float*)d_in[1];
    const int*   links   = (const int*)  d_in[2];
    const float* Wp = (const float*)d_in[5];
    const float* Up = (const float*)d_in[6];
    const float* bp = (const float*)d_in[7];
    const float* Wl = (const float*)d_in[8];
    const float* Ul = (const float*)d_in[9];
    const float* bl = (const float*)d_in[10];
    const float* D1 = (const float*)d_in[11];
    const float* b1 = (const float*)d_in[12];
    const float* D2 = (const float*)d_in[13];
    const float* b2 = (const float*)d_in[14];
    const float* Wf = (const float*)d_in[15];
    const float* bf = (const float*)d_in[16];
    float* out = (float*)d_out;

    const int pgrid = (NPATHS + 63) / 64;

    k_init<<<(NLINKS * 96 + 255) / 256, 256>>>(cap, Wp, bp);
    k_path<true, false><<<pgrid, 128>>>(links, Up, bp, traffic);
    for (int t = 1; t < 8; t++) {
        k_link<<<NLINKS / 8, 256>>>(Wl, Ul, bl, Wp, bp);
        if (t < 7)
            k_path<false, false><<<pgrid, 128>>>(links, Up, bp, traffic);
        else
            k_path<false, true><<<pgrid, 128>>>(links, Up, bp, traffic);
    }
    k_readout<<<NPATHS / 32, 128>>>(D1, b1, D2, b2, Wf, bf, out);
}

// round 15
// speedup vs baseline: 1.1435x; 1.0330x over previous
#include <cuda_runtime.h>

#define NPATHS 100000
#define NLINKS 10000

// ---------------- persistent device state ----------------
__device__ __align__(16) float g_link_state[NLINKS * 32];
__device__ __align__(16) float g_path_state[NPATHS * 32];
__device__ __align__(16) float g_m[NLINKS * 32];          // segment sums
__device__ __align__(16) float g_LG[NLINKS * 96];         // link_state @ Wp + biases

// ---------------- packed f32x2 helpers ----------------
typedef unsigned long long u64;

__device__ __forceinline__ u64 splat2(float x) {
    u64 r; asm("mov.b64 %0, {%1, %1};" : "=l"(r) : "f"(x)); return r;
}
__device__ __forceinline__ u64 pack2(float a, float b) {
    u64 r; asm("mov.b64 %0, {%1, %2};" : "=l"(r) : "f"(a), "f"(b)); return r;
}
__device__ __forceinline__ void unpack2(u64 v, float& a, float& b) {
    asm("mov.b64 {%0, %1}, %2;" : "=f"(a), "=f"(b) : "l"(v));
}
__device__ __forceinline__ void ffma2(u64& d, u64 a, u64 b) {
    asm("fma.rn.f32x2 %0, %1, %2, %0;" : "+l"(d) : "l"(a), "l"(b));
}
__device__ __forceinline__ void lds_v2(unsigned addr, u64& a, u64& b) {
    asm volatile("ld.shared.v2.u64 {%0, %1}, [%2];" : "=l"(a), "=l"(b) : "r"(addr));
}
__device__ __forceinline__ void sts_v2(unsigned addr, u64 a, u64 b) {
    asm volatile("st.shared.v2.u64 [%0], {%1, %2};" :: "r"(addr), "l"(a), "l"(b) : "memory");
}
__device__ __forceinline__ void ldg_v2(const void* p, u64& a, u64& b) {
    asm volatile("ld.global.nc.v2.u64 {%0, %1}, [%2];" : "=l"(a), "=l"(b) : "l"(p));
}

// ---------------- fast activations ----------------
__device__ __forceinline__ float tanh_ap(float x) {
    float r; asm("tanh.approx.f32 %0, %1;" : "=f"(r) : "f"(x)); return r;
}
__device__ __forceinline__ float sigmoid_t(float x) {
    return fmaf(tanh_ap(0.5f * x), 0.5f, 0.5f);
}
__device__ __forceinline__ float seluf_(float x) {
    const float sc = 1.0507009873554805f;
    const float al = 1.6732632423543772f;
    return x > 0.0f ? sc * x : sc * al * (__expf(x) - 1.0f);
}

// ---------------- init (links only): link_state, m=0, initial LG ------------
__global__ void k_init(const float* __restrict__ cap,
                       const float* __restrict__ Wp, const float* __restrict__ bp) {
    int idx = blockIdx.x * blockDim.x + threadIdx.x;
    if (idx < NLINKS * 32) {
        g_link_state[idx] = ((idx & 31) == 0) ? cap[idx >> 5] : 0.0f;
        g_m[idx] = 0.0f;
    }
    if (idx < NLINKS * 96) {
        int l = idx / 96;
        int j = idx - l * 96;
        float v = cap[l] * Wp[j] + bp[j];        // input bias bp[0]
        if (j < 64) v += bp[96 + j];             // fold recurrent bias bp[1] for z,r
        g_LG[idx] = v;
    }
}

// ---------------- path phase v10: lane=dim, warp=16 paths -------------------
// z/r gather folded into acc init; h-part of LG batch-loaded at epilogue start
// (no live-through-k-loop ph registers) -> 6 blocks/SM.
#define PPW 16          // paths per warp
#define NPAIR 8         // path pairs per warp
#define HSTRB 80u       // bytes per dim row (10 u64: 4 groups x 16B + 16B pad)

template <bool FIRST, bool LAST>
__global__ void __launch_bounds__(128, 6)
k_path(const int* __restrict__ links, const float* __restrict__ Up,
       const float* __restrict__ bp, const float* __restrict__ traffic) {
    __shared__ __align__(16) float sUp[3072];            // Up [k][j] row-major f32
    __shared__ int slinks[64 * 8];                       // 64 paths per block
    __shared__ __align__(16) char shtile[4 * 32 * HSTRB];// per warp: h[dim][group swz]

    const int tid  = threadIdx.x;
    const int lane = tid & 31;
    const int warp = tid >> 5;
    const int p0   = blockIdx.x * 64;                    // 64 paths per block

    for (int i = tid; i < 3072; i += 128) sUp[i] = Up[i];
    for (int i = tid; i < 512; i += 128) {
        int e = p0 * 8 + i;
        slinks[i] = (e < NPATHS * 8) ? links[e] : 0;
    }
    __syncthreads();

    const int pw = p0 + warp * PPW;
    if (pw >= NPATHS) return;                            // whole-warp exit

    char* shw = shtile + warp * 32 * HSTRB;
    float* shwf = reinterpret_cast<float*>(shw);
    const unsigned shw_a = (unsigned)__cvta_generic_to_shared(shw);
    const unsigned sl16 = ((unsigned)(lane >> 3) & 3u) * 16u;   // owner-dim swizzle (bytes)

    // initial h: float slot = lane*20 + (((i>>2)*4) ^ (sl16>>2)) + (i&3)
    #pragma unroll 1
    for (int i = 0; i < PPW; i++) {
        float v;
        if (FIRST) {
            v = (lane == 0) ? __ldg(traffic + pw + i) : 0.0f;
        } else {
            v = g_path_state[(pw + i) * 32 + lane];
        }
        shwf[lane * 20 + ((((unsigned)i >> 2) * 4u) ^ (sl16 >> 2)) + (i & 3)] = v;
    }
    __syncwarp();

    const u64 b1h2 = splat2(__ldg(bp + 96 + 64 + lane));
    const int* slk = slinks + warp * PPW * 8;

    #pragma unroll 1
    for (int s = 0; s < 8; s++) {
        // prologue: issue z/r gather loads, fold into acc init.
        float pz[PPW], pr[PPW];
        #pragma unroll
        for (int q = 0; q < PPW; q++) {
            const float* lg = g_LG + slk[q * 8 + s] * 96 + lane;
            pz[q] = __ldg(lg);
            pr[q] = __ldg(lg + 32);
        }

        u64 accz[NPAIR], accr[NPAIR], acch[NPAIR];
        #pragma unroll
        for (int p2 = 0; p2 < NPAIR; p2++) {
            accz[p2] = pack2(pz[2 * p2], pz[2 * p2 + 1]);
            accr[p2] = pack2(pr[2 * p2], pr[2 * p2 + 1]);
            acch[p2] = b1h2;
        }

        // recurrent matvec: acc += h @ Up
        #pragma unroll 2
        for (int k = 0; k < 32; k++) {
            const float* w = sUp + k * 96 + lane;
            u64 wz2 = splat2(w[0]);
            u64 wr2 = splat2(w[32]);
            u64 wh2 = splat2(w[64]);
            unsigned ha = shw_a + (unsigned)k * HSTRB;
            unsigned sk16 = ((unsigned)(k >> 3) & 3u) * 16u;
            #pragma unroll
            for (int g = 0; g < 4; g++) {
                u64 hA, hB;
                lds_v2(ha + (((unsigned)g * 16u) ^ sk16), hA, hB);
                ffma2(accz[2*g],   hA, wz2);
                ffma2(accz[2*g+1], hB, wz2);
                ffma2(accr[2*g],   hA, wr2);
                ffma2(accr[2*g+1], hB, wr2);
                ffma2(acch[2*g],   hA, wh2);
                ffma2(acch[2*g+1], hB, wh2);
            }
        }

        // epilogue: batch-load LG h-part, gates, state update, scatter
        float phh[PPW];
        #pragma unroll
        for (int q = 0; q < PPW; q++)
            phh[q] = __ldg(g_LG + slk[q * 8 + s] * 96 + 64 + lane);

        #pragma unroll
        for (int g = 0; g < 4; g++) {
            const int q0 = 4 * g;
            unsigned ea = shw_a + (unsigned)lane * HSTRB + (((unsigned)g * 16u) ^ sl16);
            u64 hoA2, hoB2;
            lds_v2(ea, hoA2, hoB2);
            float ho0, ho1, ho2, ho3;
            unpack2(hoA2, ho0, ho1);
            unpack2(hoB2, ho2, ho3);

            float az0, az1, az2v, az3, ar0, ar1, ar2v, ar3, ah0, ah1, ah2v, ah3;
            unpack2(accz[2*g], az0, az1);   unpack2(accz[2*g+1], az2v, az3);
            unpack2(accr[2*g], ar0, ar1);   unpack2(accr[2*g+1], ar2v, ar3);
            unpack2(acch[2*g], ah0, ah1);   unpack2(acch[2*g+1], ah2v, ah3);

            float z0 = sigmoid_t(az0);
            float r0 = sigmoid_t(ar0);
            float c0 = tanh_ap(phh[q0] + r0 * ah0);
            float hn0 = c0 + z0 * (ho0 - c0);

            float z1 = sigmoid_t(az1);
            float r1 = sigmoid_t(ar1);
            float c1 = tanh_ap(phh[q0 + 1] + r1 * ah1);
            float hn1 = c1 + z1 * (ho1 - c1);

            float z2 = sigmoid_t(az2v);
            float r2 = sigmoid_t(ar2v);
            float c2 = tanh_ap(phh[q0 + 2] + r2 * ah2v);
            float hn2 = c2 + z2 * (ho2 - c2);

            float z3 = sigmoid_t(az3);
            float r3 = sigmoid_t(ar3);
            float c3 = tanh_ap(phh[q0 + 3] + r3 * ah3);
            float hn3 = c3 + z3 * (ho3 - c3);

            sts_v2(ea, pack2(hn0, hn1), pack2(hn2, hn3));

            if (!LAST) {
                atomicAdd(g_m + slk[(q0    ) * 8 + s] * 32 + lane, hn0);
                atomicAdd(g_m + slk[(q0 + 1) * 8 + s] * 32 + lane, hn1);
                atomicAdd(g_m + slk[(q0 + 2) * 8 + s] * 32 + lane, hn2);
                atomicAdd(g_m + slk[(q0 + 3) * 8 + s] * 32 + lane, hn3);
            }
        }
        __syncwarp();
    }

    // writeback h tile (coalesced per path)
    #pragma unroll 1
    for (int i = 0; i < PPW; i++)
        g_path_state[(pw + i) * 32 + lane] =
            shwf[lane * 20 + ((((unsigned)i >> 2) * 4u) ^ (sl16 >> 2)) + (i & 3)];
}

// ---------------- link phase: warp per link, lane=dim -----------------------
__global__ void __launch_bounds__(256)
k_link(const float* __restrict__ Wl, const float* __restrict__ Ul,
       const float* __restrict__ bl, const float* __restrict__ Wp,
       const float* __restrict__ bp) {
    __shared__ float sWl[3072], sUl[3072], sWp[3072];
    __shared__ float sbl[192], sbp[192];
    const int tid = threadIdx.x;
    for (int i = tid; i < 3072; i += 256) { sWl[i] = Wl[i]; sUl[i] = Ul[i]; sWp[i] = Wp[i]; }
    if (tid < 192) { sbl[tid] = bl[tid]; sbp[tid] = bp[tid]; }
    __syncthreads();

    const int lane = tid & 31;
    const int L = blockIdx.x * 8 + (tid >> 5);        // 1250 * 8 = 10000 exact

    float mown = g_m[L * 32 + lane];
    float hown = g_link_state[L * 32 + lane];

    float az  = sbl[lane]      + sbl[96 + lane];
    float arx = sbl[32 + lane] + sbl[128 + lane];
    float axh = sbl[64 + lane];
    float ahh = sbl[160 + lane];

    #pragma unroll 1
    for (int k = 0; k < 32; k++) {
        float mk = __shfl_sync(0xffffffffu, mown, k);
        float hk = __shfl_sync(0xffffffffu, hown, k);
        const float* wl = sWl + k * 96 + lane;
        const float* ul = sUl + k * 96 + lane;
        az  = fmaf(mk, wl[0],  fmaf(hk, ul[0],  az));
        arx = fmaf(mk, wl[32], fmaf(hk, ul[32], arx));
        axh = fmaf(mk, wl[64], axh);
        ahh = fmaf(hk, ul[64], ahh);
    }

    float z  = sigmoid_t(az);
    float r  = sigmoid_t(arx);
    float c  = tanh_ap(axh + r * ahh);
    float hn = c + z * (hown - c);

    g_link_state[L * 32 + lane] = hn;
    g_m[L * 32 + lane] = 0.0f;                        // reset for next iteration

    // recompute LG = new_link_state @ Wp + biases (lane owns cols j, 32+j, 64+j)
    float l0 = sbp[lane]      + sbp[96 + lane];
    float l1 = sbp[32 + lane] + sbp[128 + lane];
    float l2 = sbp[64 + lane];
    #pragma unroll 1
    for (int k = 0; k < 32; k++) {
        float hk = __shfl_sync(0xffffffffu, hn, k);
        const float* wp = sWp + k * 96 + lane;
        l0 = fmaf(hk, wp[0],  l0);
        l1 = fmaf(hk, wp[32], l1);
        l2 = fmaf(hk, wp[64], l2);
    }
    g_LG[L * 96 + lane]      = l0;
    g_LG[L * 96 + 32 + lane] = l1;
    g_LG[L * 96 + 64 + lane] = l2;
}

// ---------------- readout: lane-contiguous columns + f32x2, pipelined D2 ----
__global__ void __launch_bounds__(128)
k_readout(const float* __restrict__ D1, const float* __restrict__ b1,
          const float* __restrict__ D2, const float* __restrict__ b2,
          const float* __restrict__ Wf, const float* __restrict__ bf,
          float* __restrict__ out) {
    __shared__ float sx1[4 * 8 * 256];   // per-warp [path][k] hidden1
    const int tid = threadIdx.x;
    const int lane = tid & 31, warp = tid >> 5;
    const int pbase = blockIdx.x * 32 + warp * 8;   // 100000 % 32 == 0
    float* myx1 = sx1 + warp * 2048;
    const int cb = 8 * lane;             // this lane's contiguous column base

    u64 bb1[4], bb2[4];
    ldg_v2(b1 + cb, bb1[0], bb1[1]);  ldg_v2(b1 + cb + 4, bb1[2], bb1[3]);
    ldg_v2(b2 + cb, bb2[0], bb2[1]);  ldg_v2(b2 + cb + 4, bb2[2], bb2[3]);

    float hsave[8];

    // ---- layer 1: 32 -> 256 + selu ----
    #pragma unroll 1
    for (int p = 0; p < 8; p++) {
        float hown = g_path_state[(pbase + p) * 32 + lane];
        hsave[p] = hown;
        u64 acc[4];
        #pragma unroll
        for (int i = 0; i < 4; i++) acc[i] = bb1[i];
        #pragma unroll 1
        for (int k = 0; k < 32; k++) {
            float hk = __shfl_sync(0xffffffffu, hown, k);
            u64 h2 = splat2(hk);
            const float* d1 = D1 + k * 256 + cb;
            u64 w0, w1, w2, w3;
            ldg_v2(d1, w0, w1); ldg_v2(d1 + 4, w2, w3);
            ffma2(acc[0], h2, w0); ffma2(acc[1], h2, w1);
            ffma2(acc[2], h2, w2); ffma2(acc[3], h2, w3);
        }
        float2* dst = reinterpret_cast<float2*>(myx1 + p * 256 + cb);
        #pragma unroll
        for (int i = 0; i < 4; i++) {
            float x0, x1; unpack2(acc[i], x0, x1);
            dst[i] = make_float2(seluf_(x0), seluf_(x1));
        }
    }
    __syncwarp();

    // ---- layer 2: 256 -> 256, f32x2, 2-stage pipelined D2 stream ----
    u64 a2p[32];
    #pragma unroll
    for (int p = 0; p < 8; p++)
        #pragma unroll
        for (int i = 0; i < 4; i++) a2p[p * 4 + i] = bb2[i];

    u64 cw0, cw1, cw2, cw3;
    {
        const float* d2 = D2 + cb;
        ldg_v2(d2, cw0, cw1); ldg_v2(d2 + 4, cw2, cw3);
    }
    #pragma unroll 2
    for (int k = 0; k < 255; k++) {
        const float* dn = D2 + (k + 1) * 256 + cb;
        u64 nw0, nw1, nw2, nw3;
        ldg_v2(dn, nw0, nw1); ldg_v2(dn + 4, nw2, nw3);
        #pragma unroll
        for (int p = 0; p < 8; p++) {
            u64 x2 = splat2(myx1[p * 256 + k]);
            ffma2(a2p[p*4+0], x2, cw0); ffma2(a2p[p*4+1], x2, cw1);
            ffma2(a2p[p*4+2], x2, cw2); ffma2(a2p[p*4+3], x2, cw3);
        }
        cw0 = nw0; cw1 = nw1; cw2 = nw2; cw3 = nw3;
    }
    #pragma unroll
    for (int p = 0; p < 8; p++) {       // k = 255 tail
        u64 x2 = splat2(myx1[p * 256 + 255]);
        ffma2(a2p[p*4+0], x2, cw0); ffma2(a2p[p*4+1], x2, cw1);
        ffma2(a2p[p*4+2], x2, cw2); ffma2(a2p[p*4+3], x2, cw3);
    }

    // ---- selu + final dense on concat(x2, h) ----
    const float2* Wf2 = reinterpret_cast<const float2*>(Wf);
    float2 wfx[8];
    #pragma unroll
    for (int i = 0; i < 8; i++) wfx[i] = __ldg(Wf2 + cb + i);
    float2 wfh = __ldg(Wf2 + 256 + lane);
    float bf0 = __ldg(bf), bf1 = __ldg(bf + 1);

    #pragma unroll 1
    for (int p = 0; p < 8; p++) {
        float hv = hsave[p];
        float s0 = hv * wfh.x, s1 = hv * wfh.y;
        #pragma unroll
        for (int i = 0; i < 4; i++) {
            float x0, x1; unpack2(a2p[p * 4 + i], x0, x1);
            x0 = seluf_(x0); x1 = seluf_(x1);
            s0 = fmaf(x0, wfx[2*i].x, fmaf(x1, wfx[2*i+1].x, s0));
            s1 = fmaf(x0, wfx[2*i].y, fmaf(x1, wfx[2*i+1].y, s1));
        }
        #pragma unroll
        for (int off = 16; off; off >>= 1) {
            s0 += __shfl_xor_sync(0xffffffffu, s0, off);
            s1 += __shfl_xor_sync(0xffffffffu, s1, off);
        }
        if (lane == 0)
            reinterpret_cast<float2*>(out)[pbase + p] = make_float2(s0 + bf0, s1 + bf1);
    }
}

// ---------------- launch ----------------
extern "C" void kernel_launch(void* const* d_in, const int* in_sizes, int n_in,
                              void* d_out, int out_size) {
    const float* cap     = (const float*)d_in[0];
    const float* traffic = (const float*)d_in[1];
    const int*   links   = (const int*)  d_in[2];
    const float* Wp = (const float*)d_in[5];
    const float* Up = (const float*)d_in[6];
    const float* bp = (const float*)d_in[7];
    const float* Wl = (const float*)d_in[8];
    const float* Ul = (const float*)d_in[9];
    const float* bl = (const float*)d_in[10];
    const float* D1 = (const float*)d_in[11];
    const float* b1 = (const float*)d_in[12];
    const float* D2 = (const float*)d_in[13];
    const float* b2 = (const float*)d_in[14];
    const float* Wf = (const float*)d_in[15];
    const float* bf = (const float*)d_in[16];
    float* out = (float*)d_out;

    const int pgrid = (NPATHS + 63) / 64;

    k_init<<<(NLINKS * 96 + 255) / 256, 256>>>(cap, Wp, bp);
    k_path<true, false><<<pgrid, 128>>>(links, Up, bp, traffic);
    for (int t = 1; t < 8; t++) {
        k_link<<<NLINKS / 8, 256>>>(Wl, Ul, bl, Wp, bp);
        if (t < 7)
            k_path<false, false><<<pgrid, 128>>>(links, Up, bp, traffic);
        else
            k_path<false, true><<<pgrid, 128>>>(links, Up, bp, traffic);
    }
    k_readout<<<NPATHS / 32, 128>>>(D1, b1, D2, b2, Wf, bf, out);
}

// round 16
// speedup vs baseline: 1.2462x; 1.0898x over previous
#include <cuda_runtime.h>

#define NPATHS 100000
#define NLINKS 10000

// ---------------- persistent device state ----------------
__device__ __align__(16) float g_link_state[NLINKS * 32];
__device__ __align__(16) float g_path_state[NPATHS * 32];
__device__ __align__(16) float g_m[NLINKS * 32];          // segment sums
__device__ __align__(16) float g_LG[NLINKS * 96];         // link_state @ Wp + biases

// ---------------- packed f32x2 helpers ----------------
typedef unsigned long long u64;

__device__ __forceinline__ u64 splat2(float x) {
    u64 r; asm("mov.b64 %0, {%1, %1};" : "=l"(r) : "f"(x)); return r;
}
__device__ __forceinline__ u64 pack2(float a, float b) {
    u64 r; asm("mov.b64 %0, {%1, %2};" : "=l"(r) : "f"(a), "f"(b)); return r;
}
__device__ __forceinline__ void unpack2(u64 v, float& a, float& b) {
    asm("mov.b64 {%0, %1}, %2;" : "=f"(a), "=f"(b) : "l"(v));
}
__device__ __forceinline__ void ffma2(u64& d, u64 a, u64 b) {
    asm("fma.rn.f32x2 %0, %1, %2, %0;" : "+l"(d) : "l"(a), "l"(b));
}
__device__ __forceinline__ void lds_v2(unsigned addr, u64& a, u64& b) {
    asm volatile("ld.shared.v2.u64 {%0, %1}, [%2];" : "=l"(a), "=l"(b) : "r"(addr));
}
__device__ __forceinline__ void sts_v2(unsigned addr, u64 a, u64 b) {
    asm volatile("st.shared.v2.u64 [%0], {%1, %2};" :: "r"(addr), "l"(a), "l"(b) : "memory");
}
__device__ __forceinline__ void ldg_v2(const void* p, u64& a, u64& b) {
    asm volatile("ld.global.nc.v2.u64 {%0, %1}, [%2];" : "=l"(a), "=l"(b) : "l"(p));
}

// ---------------- fast activations ----------------
__device__ __forceinline__ float tanh_ap(float x) {
    float r; asm("tanh.approx.f32 %0, %1;" : "=f"(r) : "f"(x)); return r;
}
__device__ __forceinline__ float sigmoid_t(float x) {
    return fmaf(tanh_ap(0.5f * x), 0.5f, 0.5f);
}
__device__ __forceinline__ float seluf_(float x) {
    const float sc = 1.0507009873554805f;
    const float al = 1.6732632423543772f;
    return x > 0.0f ? sc * x : sc * al * (__expf(x) - 1.0f);
}

// ---------------- init (links only): link_state, m=0, initial LG ------------
__global__ void k_init(const float* __restrict__ cap,
                       const float* __restrict__ Wp, const float* __restrict__ bp) {
    int idx = blockIdx.x * blockDim.x + threadIdx.x;
    if (idx < NLINKS * 32) {
        g_link_state[idx] = ((idx & 31) == 0) ? cap[idx >> 5] : 0.0f;
        g_m[idx] = 0.0f;
    }
    if (idx < NLINKS * 96) {
        int l = idx / 96;
        int j = idx - l * 96;
        float v = cap[l] * Wp[j] + bp[j];        // input bias bp[0]
        if (j < 64) v += bp[96 + j];             // fold recurrent bias bp[1] for z,r
        g_LG[idx] = v;
    }
}

// ---------------- path phase v9 (R14 best): lane=dim, warp=16 paths ---------
#define PPW 16          // paths per warp
#define NPAIR 8         // path pairs per warp
#define HSTRB 80u       // bytes per dim row (10 u64: 4 groups x 16B + 16B pad)

template <bool FIRST, bool LAST>
__global__ void __launch_bounds__(128, 5)
k_path(const int* __restrict__ links, const float* __restrict__ Up,
       const float* __restrict__ bp, const float* __restrict__ traffic) {
    __shared__ __align__(16) float sUp[3072];            // Up [k][j] row-major f32
    __shared__ int slinks[64 * 8];                       // 64 paths per block
    __shared__ __align__(16) char shtile[4 * 32 * HSTRB];// per warp: h[dim][group swz]

    const int tid  = threadIdx.x;
    const int lane = tid & 31;
    const int warp = tid >> 5;
    const int p0   = blockIdx.x * 64;                    // 64 paths per block

    for (int i = tid; i < 3072; i += 128) sUp[i] = Up[i];
    for (int i = tid; i < 512; i += 128) {
        int e = p0 * 8 + i;
        slinks[i] = (e < NPATHS * 8) ? links[e] : 0;
    }
    __syncthreads();

    const int pw = p0 + warp * PPW;
    if (pw >= NPATHS) return;                            // whole-warp exit

    char* shw = shtile + warp * 32 * HSTRB;
    float* shwf = reinterpret_cast<float*>(shw);
    const unsigned shw_a = (unsigned)__cvta_generic_to_shared(shw);
    const unsigned sl16 = ((unsigned)(lane >> 3) & 3u) * 16u;   // owner-dim swizzle (bytes)

    // initial h: float slot = lane*20 + (((i>>2)*4) ^ (sl16>>2)) + (i&3)
    #pragma unroll 1
    for (int i = 0; i < PPW; i++) {
        float v;
        if (FIRST) {
            v = (lane == 0) ? __ldg(traffic + pw + i) : 0.0f;
        } else {
            v = g_path_state[(pw + i) * 32 + lane];
        }
        shwf[lane * 20 + ((((unsigned)i >> 2) * 4u) ^ (sl16 >> 2)) + (i & 3)] = v;
    }
    __syncwarp();

    const u64 b1h2 = splat2(__ldg(bp + 96 + 64 + lane));
    const int* slk = slinks + warp * PPW * 8;

    #pragma unroll 1
    for (int s = 0; s < 8; s++) {
        // prologue: issue ALL LG gather loads, then fold z/r into acc init.
        float pz[PPW], pr[PPW], ph[PPW];
        #pragma unroll
        for (int q = 0; q < PPW; q++) {
            const float* lg = g_LG + slk[q * 8 + s] * 96 + lane;
            pz[q] = __ldg(lg);
            pr[q] = __ldg(lg + 32);
            ph[q] = __ldg(lg + 64);
        }

        u64 accz[NPAIR], accr[NPAIR], acch[NPAIR];
        #pragma unroll
        for (int p2 = 0; p2 < NPAIR; p2++) {
            accz[p2] = pack2(pz[2 * p2], pz[2 * p2 + 1]);
            accr[p2] = pack2(pr[2 * p2], pr[2 * p2 + 1]);
            acch[p2] = b1h2;
        }

        // recurrent matvec: acc += h @ Up
        #pragma unroll 2
        for (int k = 0; k < 32; k++) {
            const float* w = sUp + k * 96 + lane;
            u64 wz2 = splat2(w[0]);
            u64 wr2 = splat2(w[32]);
            u64 wh2 = splat2(w[64]);
            unsigned ha = shw_a + (unsigned)k * HSTRB;
            unsigned sk16 = ((unsigned)(k >> 3) & 3u) * 16u;
            #pragma unroll
            for (int g = 0; g < 4; g++) {
                u64 hA, hB;
                lds_v2(ha + (((unsigned)g * 16u) ^ sk16), hA, hB);
                ffma2(accz[2*g],   hA, wz2);
                ffma2(accz[2*g+1], hB, wz2);
                ffma2(accr[2*g],   hA, wr2);
                ffma2(accr[2*g+1], hB, wr2);
                ffma2(acch[2*g],   hA, wh2);
                ffma2(acch[2*g+1], hB, wh2);
            }
        }

        // epilogue: gates, state update, (conditional) coalesced scatter
        #pragma unroll
        for (int g = 0; g < 4; g++) {
            const int q0 = 4 * g;
            unsigned ea = shw_a + (unsigned)lane * HSTRB + (((unsigned)g * 16u) ^ sl16);
            u64 hoA2, hoB2;
            lds_v2(ea, hoA2, hoB2);
            float ho0, ho1, ho2, ho3;
            unpack2(hoA2, ho0, ho1);
            unpack2(hoB2, ho2, ho3);

            float az0, az1, az2v, az3, ar0, ar1, ar2v, ar3, ah0, ah1, ah2v, ah3;
            unpack2(accz[2*g], az0, az1);   unpack2(accz[2*g+1], az2v, az3);
            unpack2(accr[2*g], ar0, ar1);   unpack2(accr[2*g+1], ar2v, ar3);
            unpack2(acch[2*g], ah0, ah1);   unpack2(acch[2*g+1], ah2v, ah3);

            float z0 = sigmoid_t(az0);
            float r0 = sigmoid_t(ar0);
            float c0 = tanh_ap(ph[q0] + r0 * ah0);
            float hn0 = c0 + z0 * (ho0 - c0);

            float z1 = sigmoid_t(az1);
            float r1 = sigmoid_t(ar1);
            float c1 = tanh_ap(ph[q0 + 1] + r1 * ah1);
            float hn1 = c1 + z1 * (ho1 - c1);

            float z2 = sigmoid_t(az2v);
            float r2 = sigmoid_t(ar2v);
            float c2 = tanh_ap(ph[q0 + 2] + r2 * ah2v);
            float hn2 = c2 + z2 * (ho2 - c2);

            float z3 = sigmoid_t(az3);
            float r3 = sigmoid_t(ar3);
            float c3 = tanh_ap(ph[q0 + 3] + r3 * ah3);
            float hn3 = c3 + z3 * (ho3 - c3);

            sts_v2(ea, pack2(hn0, hn1), pack2(hn2, hn3));

            if (!LAST) {
                atomicAdd(g_m + slk[(q0    ) * 8 + s] * 32 + lane, hn0);
                atomicAdd(g_m + slk[(q0 + 1) * 8 + s] * 32 + lane, hn1);
                atomicAdd(g_m + slk[(q0 + 2) * 8 + s] * 32 + lane, hn2);
                atomicAdd(g_m + slk[(q0 + 3) * 8 + s] * 32 + lane, hn3);
            }
        }
        __syncwarp();
    }

    // writeback h tile (coalesced per path)
    #pragma unroll 1
    for (int i = 0; i < PPW; i++)
        g_path_state[(pw + i) * 32 + lane] =
            shwf[lane * 20 + ((((unsigned)i >> 2) * 4u) ^ (sl16 >> 2)) + (i & 3)];
}

// ---------------- link phase: warp per link, lane=dim -----------------------
__global__ void __launch_bounds__(256)
k_link(const float* __restrict__ Wl, const float* __restrict__ Ul,
       const float* __restrict__ bl, const float* __restrict__ Wp,
       const float* __restrict__ bp) {
    __shared__ float sWl[3072], sUl[3072], sWp[3072];
    __shared__ float sbl[192], sbp[192];
    const int tid = threadIdx.x;
    for (int i = tid; i < 3072; i += 256) { sWl[i] = Wl[i]; sUl[i] = Ul[i]; sWp[i] = Wp[i]; }
    if (tid < 192) { sbl[tid] = bl[tid]; sbp[tid] = bp[tid]; }
    __syncthreads();

    const int lane = tid & 31;
    const int L = blockIdx.x * 8 + (tid >> 5);        // 1250 * 8 = 10000 exact

    float mown = g_m[L * 32 + lane];
    float hown = g_link_state[L * 32 + lane];

    float az  = sbl[lane]      + sbl[96 + lane];
    float arx = sbl[32 + lane] + sbl[128 + lane];
    float axh = sbl[64 + lane];
    float ahh = sbl[160 + lane];

    #pragma unroll 1
    for (int k = 0; k < 32; k++) {
        float mk = __shfl_sync(0xffffffffu, mown, k);
        float hk = __shfl_sync(0xffffffffu, hown, k);
        const float* wl = sWl + k * 96 + lane;
        const float* ul = sUl + k * 96 + lane;
        az  = fmaf(mk, wl[0],  fmaf(hk, ul[0],  az));
        arx = fmaf(mk, wl[32], fmaf(hk, ul[32], arx));
        axh = fmaf(mk, wl[64], axh);
        ahh = fmaf(hk, ul[64], ahh);
    }

    float z  = sigmoid_t(az);
    float r  = sigmoid_t(arx);
    float c  = tanh_ap(axh + r * ahh);
    float hn = c + z * (hown - c);

    g_link_state[L * 32 + lane] = hn;
    g_m[L * 32 + lane] = 0.0f;                        // reset for next iteration

    // recompute LG = new_link_state @ Wp + biases (lane owns cols j, 32+j, 64+j)
    float l0 = sbp[lane]      + sbp[96 + lane];
    float l1 = sbp[32 + lane] + sbp[128 + lane];
    float l2 = sbp[64 + lane];
    #pragma unroll 1
    for (int k = 0; k < 32; k++) {
        float hk = __shfl_sync(0xffffffffu, hn, k);
        const float* wp = sWp + k * 96 + lane;
        l0 = fmaf(hk, wp[0],  l0);
        l1 = fmaf(hk, wp[32], l1);
        l2 = fmaf(hk, wp[64], l2);
    }
    g_LG[L * 96 + lane]      = l0;
    g_LG[L * 96 + 32 + lane] = l1;
    g_LG[L * 96 + 64 + lane] = l2;
}

// ---------------- readout v3: smem-staged weights, 64 paths/block -----------
// Dynamic smem: wtile[8192] floats (32x256 weight rows) + sx1[8][2048].
__global__ void __launch_bounds__(256, 2)
k_readout(const float* __restrict__ D1, const float* __restrict__ b1,
          const float* __restrict__ D2, const float* __restrict__ b2,
          const float* __restrict__ Wf, const float* __restrict__ bf,
          float* __restrict__ out) {
    extern __shared__ float smem[];
    float* wtile = smem;                 // 32 KB staging for D1 / D2 tiles
    float* sx1   = smem + 8192;          // 64 KB per-warp x1

    const int tid = threadIdx.x;
    const int lane = tid & 31, warp = tid >> 5;
    const int pbase = blockIdx.x * 64 + warp * 8;
    const bool active = pbase < NPATHS;  // 100000 = 1562*64 + 32: last block warps 4-7 idle
    float* myx1 = sx1 + warp * 2048;
    const int cb = 8 * lane;
    const unsigned wt_a = (unsigned)__cvta_generic_to_shared(wtile) + (unsigned)cb * 4u;

    // cooperative load of D1 (32x256) into wtile
    {
        const float4* src = reinterpret_cast<const float4*>(D1);
        float4* dst = reinterpret_cast<float4*>(wtile);
        #pragma unroll
        for (int i = 0; i < 8; i++) dst[tid + 256 * i] = __ldg(src + tid + 256 * i);
    }

    u64 bb1[4], bb2[4];
    ldg_v2(b1 + cb, bb1[0], bb1[1]);  ldg_v2(b1 + cb + 4, bb1[2], bb1[3]);
    ldg_v2(b2 + cb, bb2[0], bb2[1]);  ldg_v2(b2 + cb + 4, bb2[2], bb2[3]);

    float hsave[8];
    if (active) {
        #pragma unroll
        for (int p = 0; p < 8; p++)
            hsave[p] = g_path_state[(pbase + p) * 32 + lane];
    }
    __syncthreads();

    // ---- layer 1: 32 -> 256 from smem, weight-row reuse across 8 paths ----
    u64 acc[32];
    if (active) {
        #pragma unroll
        for (int p = 0; p < 8; p++)
            #pragma unroll
            for (int i = 0; i < 4; i++) acc[p * 4 + i] = bb1[i];
        #pragma unroll 1
        for (int k = 0; k < 32; k++) {
            u64 w0, w1, w2, w3;
            unsigned wa = wt_a + (unsigned)k * 1024u;
            lds_v2(wa, w0, w1);
            lds_v2(wa + 16u, w2, w3);
            #pragma unroll
            for (int p = 0; p < 8; p++) {
                u64 x2 = splat2(__shfl_sync(0xffffffffu, hsave[p], k));
                ffma2(acc[p*4+0], x2, w0); ffma2(acc[p*4+1], x2, w1);
                ffma2(acc[p*4+2], x2, w2); ffma2(acc[p*4+3], x2, w3);
            }
        }
        #pragma unroll
        for (int p = 0; p < 8; p++) {
            float2* dst = reinterpret_cast<float2*>(myx1 + p * 256 + cb);
            #pragma unroll
            for (int i = 0; i < 4; i++) {
                float x0, x1; unpack2(acc[p * 4 + i], x0, x1);
                dst[i] = make_float2(seluf_(x0), seluf_(x1));
            }
        }
    }
    __syncthreads();   // wtile about to be overwritten; sx1 per-warp private

    // ---- layer 2: 256 -> 256 in 8 smem tiles of 32 rows ----
    if (active) {
        #pragma unroll
        for (int p = 0; p < 8; p++)
            #pragma unroll
            for (int i = 0; i < 4; i++) acc[p * 4 + i] = bb2[i];
    }
    #pragma unroll 1
    for (int kt = 0; kt < 8; kt++) {
        {
            const float4* src = reinterpret_cast<const float4*>(D2 + kt * 32 * 256);
            float4* dst = reinterpret_cast<float4*>(wtile);
            #pragma unroll
            for (int i = 0; i < 8; i++) dst[tid + 256 * i] = __ldg(src + tid + 256 * i);
        }
        __syncthreads();
        if (active) {
            const float* xk = myx1 + kt * 32;
            #pragma unroll 1
            for (int kk = 0; kk < 32; kk++) {
                u64 w0, w1, w2, w3;
                unsigned wa = wt_a + (unsigned)kk * 1024u;
                lds_v2(wa, w0, w1);
                lds_v2(wa + 16u, w2, w3);
                #pragma unroll
                for (int p = 0; p < 8; p++) {
                    u64 x2 = splat2(xk[p * 256 + kk]);
                    ffma2(acc[p*4+0], x2, w0); ffma2(acc[p*4+1], x2, w1);
                    ffma2(acc[p*4+2], x2, w2); ffma2(acc[p*4+3], x2, w3);
                }
            }
        }
        __syncthreads();
    }

    // ---- selu + final dense on concat(x2, h) ----
    if (active) {
        const float2* Wf2 = reinterpret_cast<const float2*>(Wf);
        float2 wfx[8];
        #pragma unroll
        for (int i = 0; i < 8; i++) wfx[i] = __ldg(Wf2 + cb + i);
        float2 wfh = __ldg(Wf2 + 256 + lane);
        float bf0 = __ldg(bf), bf1 = __ldg(bf + 1);

        #pragma unroll 1
        for (int p = 0; p < 8; p++) {
            float hv = hsave[p];
            float s0 = hv * wfh.x, s1 = hv * wfh.y;
            #pragma unroll
            for (int i = 0; i < 4; i++) {
                float x0, x1; unpack2(acc[p * 4 + i], x0, x1);
                x0 = seluf_(x0); x1 = seluf_(x1);
                s0 = fmaf(x0, wfx[2*i].x, fmaf(x1, wfx[2*i+1].x, s0));
                s1 = fmaf(x0, wfx[2*i].y, fmaf(x1, wfx[2*i+1].y, s1));
            }
            #pragma unroll
            for (int off = 16; off; off >>= 1) {
                s0 += __shfl_xor_sync(0xffffffffu, s0, off);
                s1 += __shfl_xor_sync(0xffffffffu, s1, off);
            }
            if (lane == 0)
                reinterpret_cast<float2*>(out)[pbase + p] = make_float2(s0 + bf0, s1 + bf1);
        }
    }
}

// ---------------- launch ----------------
extern "C" void kernel_launch(void* const* d_in, const int* in_sizes, int n_in,
                              void* d_out, int out_size) {
    const float* cap     = (const float*)d_in[0];
    const float* traffic = (const float*)d_in[1];
    const int*   links   = (const int*)  d_in[2];
    const float* Wp = (const float*)d_in[5];
    const float* Up = (const float*)d_in[6];
    const float* bp = (const float*)d_in[7];
    const float* Wl = (const float*)d_in[8];
    const float* Ul = (const float*)d_in[9];
    const float* bl = (const float*)d_in[10];
    const float* D1 = (const float*)d_in[11];
    const float* b1 = (const float*)d_in[12];
    const float* D2 = (const float*)d_in[13];
    const float* b2 = (const float*)d_in[14];
    const float* Wf = (const float*)d_in[15];
    const float* bf = (const float*)d_in[16];
    float* out = (float*)d_out;

    const int pgrid = (NPATHS + 63) / 64;
    const int rsmem = (8192 + 8 * 2048) * 4;   // 96 KB dynamic

    static bool attr_done = false;
    if (!attr_done) {
        cudaFuncSetAttribute(k_readout, cudaFuncAttributeMaxDynamicSharedMemorySize, rsmem);
        attr_done = true;
    }

    k_init<<<(NLINKS * 96 + 255) / 256, 256>>>(cap, Wp, bp);
    k_path<true, false><<<pgrid, 128>>>(links, Up, bp, traffic);
    for (int t = 1; t < 8; t++) {
        k_link<<<NLINKS / 8, 256>>>(Wl, Ul, bl, Wp, bp);
        if (t < 7)
            k_path<false, false><<<pgrid, 128>>>(links, Up, bp, traffic);
        else
            k_path<false, true><<<pgrid, 128>>>(links, Up, bp, traffic);
    }
    k_readout<<<(NPATHS + 63) / 64, 256, rsmem>>>(D1, b1, D2, b2, Wf, bf, out);
}

// round 17
// speedup vs baseline: 1.2581x; 1.0096x over previous
#include <cuda_runtime.h>

#define NPATHS 100000
#define NLINKS 10000

// ---------------- persistent device state ----------------
__device__ __align__(16) float g_link_state[NLINKS * 32];
__device__ __align__(16) float g_path_state[NPATHS * 32];
__device__ __align__(16) float g_m[NLINKS * 32];          // segment sums
__device__ __align__(16) float g_LG[NLINKS * 96];         // link_state @ Wp + biases

// ---------------- packed f32x2 helpers ----------------
typedef unsigned long long u64;

__device__ __forceinline__ u64 splat2(float x) {
    u64 r; asm("mov.b64 %0, {%1, %1};" : "=l"(r) : "f"(x)); return r;
}
__device__ __forceinline__ u64 pack2(float a, float b) {
    u64 r; asm("mov.b64 %0, {%1, %2};" : "=l"(r) : "f"(a), "f"(b)); return r;
}
__device__ __forceinline__ void unpack2(u64 v, float& a, float& b) {
    asm("mov.b64 {%0, %1}, %2;" : "=f"(a), "=f"(b) : "l"(v));
}
__device__ __forceinline__ void ffma2(u64& d, u64 a, u64 b) {
    asm("fma.rn.f32x2 %0, %1, %2, %0;" : "+l"(d) : "l"(a), "l"(b));
}
__device__ __forceinline__ void lds_v2(unsigned addr, u64& a, u64& b) {
    asm volatile("ld.shared.v2.u64 {%0, %1}, [%2];" : "=l"(a), "=l"(b) : "r"(addr));
}
__device__ __forceinline__ void sts_v2(unsigned addr, u64 a, u64 b) {
    asm volatile("st.shared.v2.u64 [%0], {%1, %2};" :: "r"(addr), "l"(a), "l"(b) : "memory");
}
__device__ __forceinline__ void ldg_v2(const void* p, u64& a, u64& b) {
    asm volatile("ld.global.nc.v2.u64 {%0, %1}, [%2];" : "=l"(a), "=l"(b) : "l"(p));
}

// ---------------- fast activations ----------------
__device__ __forceinline__ float tanh_ap(float x) {
    float r; asm("tanh.approx.f32 %0, %1;" : "=f"(r) : "f"(x)); return r;
}
__device__ __forceinline__ float sigmoid_t(float x) {
    return fmaf(tanh_ap(0.5f * x), 0.5f, 0.5f);
}
__device__ __forceinline__ float seluf_(float x) {
    const float sc = 1.0507009873554805f;
    const float al = 1.6732632423543772f;
    return x > 0.0f ? sc * x : sc * al * (__expf(x) - 1.0f);
}

// ---------------- init (links only): link_state, m=0, initial LG ------------
__global__ void k_init(const float* __restrict__ cap,
                       const float* __restrict__ Wp, const float* __restrict__ bp) {
    int idx = blockIdx.x * blockDim.x + threadIdx.x;
    if (idx < NLINKS * 32) {
        g_link_state[idx] = ((idx & 31) == 0) ? cap[idx >> 5] : 0.0f;
        g_m[idx] = 0.0f;
    }
    if (idx < NLINKS * 96) {
        int l = idx / 96;
        int j = idx - l * 96;
        float v = cap[l] * Wp[j] + bp[j];        // input bias bp[0]
        if (j < 64) v += bp[96 + j];             // fold recurrent bias bp[1] for z,r
        g_LG[idx] = v;
    }
}

// ---------------- path phase v9 (R14 best): lane=dim, warp=16 paths ---------
#define PPW 16          // paths per warp
#define NPAIR 8         // path pairs per warp
#define HSTRB 80u       // bytes per dim row (10 u64: 4 groups x 16B + 16B pad)

template <bool FIRST, bool LAST>
__global__ void __launch_bounds__(128, 5)
k_path(const int* __restrict__ links, const float* __restrict__ Up,
       const float* __restrict__ bp, const float* __restrict__ traffic) {
    __shared__ __align__(16) float sUp[3072];            // Up [k][j] row-major f32
    __shared__ int slinks[64 * 8];                       // 64 paths per block
    __shared__ __align__(16) char shtile[4 * 32 * HSTRB];// per warp: h[dim][group swz]

    const int tid  = threadIdx.x;
    const int lane = tid & 31;
    const int warp = tid >> 5;
    const int p0   = blockIdx.x * 64;                    // 64 paths per block

    for (int i = tid; i < 3072; i += 128) sUp[i] = Up[i];
    for (int i = tid; i < 512; i += 128) {
        int e = p0 * 8 + i;
        slinks[i] = (e < NPATHS * 8) ? links[e] : 0;
    }
    __syncthreads();

    const int pw = p0 + warp * PPW;
    if (pw >= NPATHS) return;                            // whole-warp exit

    char* shw = shtile + warp * 32 * HSTRB;
    float* shwf = reinterpret_cast<float*>(shw);
    const unsigned shw_a = (unsigned)__cvta_generic_to_shared(shw);
    const unsigned sl16 = ((unsigned)(lane >> 3) & 3u) * 16u;   // owner-dim swizzle (bytes)

    // initial h: float slot = lane*20 + (((i>>2)*4) ^ (sl16>>2)) + (i&3)
    #pragma unroll 1
    for (int i = 0; i < PPW; i++) {
        float v;
        if (FIRST) {
            v = (lane == 0) ? __ldg(traffic + pw + i) : 0.0f;
        } else {
            v = g_path_state[(pw + i) * 32 + lane];
        }
        shwf[lane * 20 + ((((unsigned)i >> 2) * 4u) ^ (sl16 >> 2)) + (i & 3)] = v;
    }
    __syncwarp();

    const u64 b1h2 = splat2(__ldg(bp + 96 + 64 + lane));
    const int* slk = slinks + warp * PPW * 8;

    #pragma unroll 1
    for (int s = 0; s < 8; s++) {
        // prologue: issue ALL LG gather loads, then fold z/r into acc init.
        float pz[PPW], pr[PPW], ph[PPW];
        #pragma unroll
        for (int q = 0; q < PPW; q++) {
            const float* lg = g_LG + slk[q * 8 + s] * 96 + lane;
            pz[q] = __ldg(lg);
            pr[q] = __ldg(lg + 32);
            ph[q] = __ldg(lg + 64);
        }

        u64 accz[NPAIR], accr[NPAIR], acch[NPAIR];
        #pragma unroll
        for (int p2 = 0; p2 < NPAIR; p2++) {
            accz[p2] = pack2(pz[2 * p2], pz[2 * p2 + 1]);
            accr[p2] = pack2(pr[2 * p2], pr[2 * p2 + 1]);
            acch[p2] = b1h2;
        }

        // recurrent matvec: acc += h @ Up
        #pragma unroll 2
        for (int k = 0; k < 32; k++) {
            const float* w = sUp + k * 96 + lane;
            u64 wz2 = splat2(w[0]);
            u64 wr2 = splat2(w[32]);
            u64 wh2 = splat2(w[64]);
            unsigned ha = shw_a + (unsigned)k * HSTRB;
            unsigned sk16 = ((unsigned)(k >> 3) & 3u) * 16u;
            #pragma unroll
            for (int g = 0; g < 4; g++) {
                u64 hA, hB;
                lds_v2(ha + (((unsigned)g * 16u) ^ sk16), hA, hB);
                ffma2(accz[2*g],   hA, wz2);
                ffma2(accz[2*g+1], hB, wz2);
                ffma2(accr[2*g],   hA, wr2);
                ffma2(accr[2*g+1], hB, wr2);
                ffma2(acch[2*g],   hA, wh2);
                ffma2(acch[2*g+1], hB, wh2);
            }
        }

        // epilogue: gates, state update, (conditional) coalesced scatter
        #pragma unroll
        for (int g = 0; g < 4; g++) {
            const int q0 = 4 * g;
            unsigned ea = shw_a + (unsigned)lane * HSTRB + (((unsigned)g * 16u) ^ sl16);
            u64 hoA2, hoB2;
            lds_v2(ea, hoA2, hoB2);
            float ho0, ho1, ho2, ho3;
            unpack2(hoA2, ho0, ho1);
            unpack2(hoB2, ho2, ho3);

            float az0, az1, az2v, az3, ar0, ar1, ar2v, ar3, ah0, ah1, ah2v, ah3;
            unpack2(accz[2*g], az0, az1);   unpack2(accz[2*g+1], az2v, az3);
            unpack2(accr[2*g], ar0, ar1);   unpack2(accr[2*g+1], ar2v, ar3);
            unpack2(acch[2*g], ah0, ah1);   unpack2(acch[2*g+1], ah2v, ah3);

            float z0 = sigmoid_t(az0);
            float r0 = sigmoid_t(ar0);
            float c0 = tanh_ap(ph[q0] + r0 * ah0);
            float hn0 = c0 + z0 * (ho0 - c0);

            float z1 = sigmoid_t(az1);
            float r1 = sigmoid_t(ar1);
            float c1 = tanh_ap(ph[q0 + 1] + r1 * ah1);
            float hn1 = c1 + z1 * (ho1 - c1);

            float z2 = sigmoid_t(az2v);
            float r2 = sigmoid_t(ar2v);
            float c2 = tanh_ap(ph[q0 + 2] + r2 * ah2v);
            float hn2 = c2 + z2 * (ho2 - c2);

            float z3 = sigmoid_t(az3);
            float r3 = sigmoid_t(ar3);
            float c3 = tanh_ap(ph[q0 + 3] + r3 * ah3);
            float hn3 = c3 + z3 * (ho3 - c3);

            sts_v2(ea, pack2(hn0, hn1), pack2(hn2, hn3));

            if (!LAST) {
                atomicAdd(g_m + slk[(q0    ) * 8 + s] * 32 + lane, hn0);
                atomicAdd(g_m + slk[(q0 + 1) * 8 + s] * 32 + lane, hn1);
                atomicAdd(g_m + slk[(q0 + 2) * 8 + s] * 32 + lane, hn2);
                atomicAdd(g_m + slk[(q0 + 3) * 8 + s] * 32 + lane, hn3);
            }
        }
        __syncwarp();
    }

    // writeback h tile (coalesced per path)
    #pragma unroll 1
    for (int i = 0; i < PPW; i++)
        g_path_state[(pw + i) * 32 + lane] =
            shwf[lane * 20 + ((((unsigned)i >> 2) * 4u) ^ (sl16 >> 2)) + (i & 3)];
}

// ---------------- link phase v4: warp per link, direct L1-cached weights ----
// No smem staging: 36 KB weight set is L1-resident per SM after warm-up.
__global__ void __launch_bounds__(256)
k_link(const float* __restrict__ Wl, const float* __restrict__ Ul,
       const float* __restrict__ bl, const float* __restrict__ Wp,
       const float* __restrict__ bp) {
    const int lane = threadIdx.x & 31;
    const int L = blockIdx.x * 8 + (threadIdx.x >> 5);   // 1250 * 8 = 10000 exact

    float mown = g_m[L * 32 + lane];
    float hown = g_link_state[L * 32 + lane];

    float az  = __ldg(bl + lane)      + __ldg(bl + 96 + lane);
    float arx = __ldg(bl + 32 + lane) + __ldg(bl + 128 + lane);
    float axh = __ldg(bl + 64 + lane);
    float ahh = __ldg(bl + 160 + lane);

    #pragma unroll 4
    for (int k = 0; k < 32; k++) {
        float mk = __shfl_sync(0xffffffffu, mown, k);
        float hk = __shfl_sync(0xffffffffu, hown, k);
        const float* wl = Wl + k * 96 + lane;
        const float* ul = Ul + k * 96 + lane;
        az  = fmaf(mk, __ldg(wl),      fmaf(hk, __ldg(ul),      az));
        arx = fmaf(mk, __ldg(wl + 32), fmaf(hk, __ldg(ul + 32), arx));
        axh = fmaf(mk, __ldg(wl + 64), axh);
        ahh = fmaf(hk, __ldg(ul + 64), ahh);
    }

    float z  = sigmoid_t(az);
    float r  = sigmoid_t(arx);
    float c  = tanh_ap(axh + r * ahh);
    float hn = c + z * (hown - c);

    g_link_state[L * 32 + lane] = hn;
    g_m[L * 32 + lane] = 0.0f;                        // reset for next iteration

    // recompute LG = new_link_state @ Wp + biases (lane owns cols j, 32+j, 64+j)
    float l0 = __ldg(bp + lane)      + __ldg(bp + 96 + lane);
    float l1 = __ldg(bp + 32 + lane) + __ldg(bp + 128 + lane);
    float l2 = __ldg(bp + 64 + lane);
    #pragma unroll 4
    for (int k = 0; k < 32; k++) {
        float hk = __shfl_sync(0xffffffffu, hn, k);
        const float* wp = Wp + k * 96 + lane;
        l0 = fmaf(hk, __ldg(wp),      l0);
        l1 = fmaf(hk, __ldg(wp + 32), l1);
        l2 = fmaf(hk, __ldg(wp + 64), l2);
    }
    g_LG[L * 96 + lane]      = l0;
    g_LG[L * 96 + 32 + lane] = l1;
    g_LG[L * 96 + 64 + lane] = l2;
}

// ---------------- readout v3: smem-staged weights, 64 paths/block -----------
// Dynamic smem: wtile[8192] floats (32x256 weight rows) + sx1[8][2048].
__global__ void __launch_bounds__(256, 2)
k_readout(const float* __restrict__ D1, const float* __restrict__ b1,
          const float* __restrict__ D2, const float* __restrict__ b2,
          const float* __restrict__ Wf, const float* __restrict__ bf,
          float* __restrict__ out) {
    extern __shared__ float smem[];
    float* wtile = smem;                 // 32 KB staging for D1 / D2 tiles
    float* sx1   = smem + 8192;          // 64 KB per-warp x1

    const int tid = threadIdx.x;
    const int lane = tid & 31, warp = tid >> 5;
    const int pbase = blockIdx.x * 64 + warp * 8;
    const bool active = pbase < NPATHS;  // 100000 = 1562*64 + 32: last block warps 4-7 idle
    float* myx1 = sx1 + warp * 2048;
    const int cb = 8 * lane;
    const unsigned wt_a = (unsigned)__cvta_generic_to_shared(wtile) + (unsigned)cb * 4u;

    // cooperative load of D1 (32x256) into wtile
    {
        const float4* src = reinterpret_cast<const float4*>(D1);
        float4* dst = reinterpret_cast<float4*>(wtile);
        #pragma unroll
        for (int i = 0; i < 8; i++) dst[tid + 256 * i] = __ldg(src + tid + 256 * i);
    }

    u64 bb1[4], bb2[4];
    ldg_v2(b1 + cb, bb1[0], bb1[1]);  ldg_v2(b1 + cb + 4, bb1[2], bb1[3]);
    ldg_v2(b2 + cb, bb2[0], bb2[1]);  ldg_v2(b2 + cb + 4, bb2[2], bb2[3]);

    float hsave[8];
    if (active) {
        #pragma unroll
        for (int p = 0; p < 8; p++)
            hsave[p] = g_path_state[(pbase + p) * 32 + lane];
    }
    __syncthreads();

    // ---- layer 1: 32 -> 256 from smem, weight-row reuse across 8 paths ----
    u64 acc[32];
    if (active) {
        #pragma unroll
        for (int p = 0; p < 8; p++)
            #pragma unroll
            for (int i = 0; i < 4; i++) acc[p * 4 + i] = bb1[i];
        #pragma unroll 1
        for (int k = 0; k < 32; k++) {
            u64 w0, w1, w2, w3;
            unsigned wa = wt_a + (unsigned)k * 1024u;
            lds_v2(wa, w0, w1);
            lds_v2(wa + 16u, w2, w3);
            #pragma unroll
            for (int p = 0; p < 8; p++) {
                u64 x2 = splat2(__shfl_sync(0xffffffffu, hsave[p], k));
                ffma2(acc[p*4+0], x2, w0); ffma2(acc[p*4+1], x2, w1);
                ffma2(acc[p*4+2], x2, w2); ffma2(acc[p*4+3], x2, w3);
            }
        }
        #pragma unroll
        for (int p = 0; p < 8; p++) {
            float2* dst = reinterpret_cast<float2*>(myx1 + p * 256 + cb);
            #pragma unroll
            for (int i = 0; i < 4; i++) {
                float x0, x1; unpack2(acc[p * 4 + i], x0, x1);
                dst[i] = make_float2(seluf_(x0), seluf_(x1));
            }
        }
    }
    __syncthreads();   // wtile about to be overwritten; sx1 per-warp private

    // ---- layer 2: 256 -> 256 in 8 smem tiles of 32 rows ----
    if (active) {
        #pragma unroll
        for (int p = 0; p < 8; p++)
            #pragma unroll
            for (int i = 0; i < 4; i++) acc[p * 4 + i] = bb2[i];
    }
    #pragma unroll 1
    for (int kt = 0; kt < 8; kt++) {
        {
            const float4* src = reinterpret_cast<const float4*>(D2 + kt * 32 * 256);
            float4* dst = reinterpret_cast<float4*>(wtile);
            #pragma unroll
            for (int i = 0; i < 8; i++) dst[tid + 256 * i] = __ldg(src + tid + 256 * i);
        }
        __syncthreads();
        if (active) {
            const float* xk = myx1 + kt * 32;
            #pragma unroll 1
            for (int kk = 0; kk < 32; kk++) {
                u64 w0, w1, w2, w3;
                unsigned wa = wt_a + (unsigned)kk * 1024u;
                lds_v2(wa, w0, w1);
                lds_v2(wa + 16u, w2, w3);
                #pragma unroll
                for (int p = 0; p < 8; p++) {
                    u64 x2 = splat2(xk[p * 256 + kk]);
                    ffma2(acc[p*4+0], x2, w0); ffma2(acc[p*4+1], x2, w1);
                    ffma2(acc[p*4+2], x2, w2); ffma2(acc[p*4+3], x2, w3);
                }
            }
        }
        __syncthreads();
    }

    // ---- selu + final dense on concat(x2, h) ----
    if (active) {
        const float2* Wf2 = reinterpret_cast<const float2*>(Wf);
        float2 wfx[8];
        #pragma unroll
        for (int i = 0; i < 8; i++) wfx[i] = __ldg(Wf2 + cb + i);
        float2 wfh = __ldg(Wf2 + 256 + lane);
        float bf0 = __ldg(bf), bf1 = __ldg(bf + 1);

        #pragma unroll 1
        for (int p = 0; p < 8; p++) {
            float hv = hsave[p];
            float s0 = hv * wfh.x, s1 = hv * wfh.y;
            #pragma unroll
            for (int i = 0; i < 4; i++) {
                float x0, x1; unpack2(acc[p * 4 + i], x0, x1);
                x0 = seluf_(x0); x1 = seluf_(x1);
                s0 = fmaf(x0, wfx[2*i].x, fmaf(x1, wfx[2*i+1].x, s0));
                s1 = fmaf(x0, wfx[2*i].y, fmaf(x1, wfx[2*i+1].y, s1));
            }
            #pragma unroll
            for (int off = 16; off; off >>= 1) {
                s0 += __shfl_xor_sync(0xffffffffu, s0, off);
                s1 += __shfl_xor_sync(0xffffffffu, s1, off);
            }
            if (lane == 0)
                reinterpret_cast<float2*>(out)[pbase + p] = make_float2(s0 + bf0, s1 + bf1);
        }
    }
}

// ---------------- launch ----------------
extern "C" void kernel_launch(void* const* d_in, const int* in_sizes, int n_in,
                              void* d_out, int out_size) {
    const float* cap     = (const float*)d_in[0];
    const float* traffic = (const float*)d_in[1];
    const int*   links   = (const int*)  d_in[2];
    const float* Wp = (const float*)d_in[5];
    const float* Up = (const float*)d_in[6];
    const float* bp = (const float*)d_in[7];
    const float* Wl = (const float*)d_in[8];
    const float* Ul = (const float*)d_in[9];
    const float* bl = (const float*)d_in[10];
    const float* D1 = (const float*)d_in[11];
    const float* b1 = (const float*)d_in[12];
    const float* D2 = (const float*)d_in[13];
    const float* b2 = (const float*)d_in[14];
    const float* Wf = (const float*)d_in[15];
    const float* bf = (const float*)d_in[16];
    float* out = (float*)d_out;

    const int pgrid = (NPATHS + 63) / 64;
    const int rsmem = (8192 + 8 * 2048) * 4;   // 96 KB dynamic

    static bool attr_done = false;
    if (!attr_done) {
        cudaFuncSetAttribute(k_readout, cudaFuncAttributeMaxDynamicSharedMemorySize, rsmem);
        attr_done = true;
    }

    k_init<<<(NLINKS * 96 + 255) / 256, 256>>>(cap, Wp, bp);
    k_path<true, false><<<pgrid, 128>>>(links, Up, bp, traffic);
    for (int t = 1; t < 8; t++) {
        k_link<<<NLINKS / 8, 256>>>(Wl, Ul, bl, Wp, bp);
        if (t < 7)
            k_path<false, false><<<pgrid, 128>>>(links, Up, bp, traffic);
        else
            k_path<false, true><<<pgrid, 128>>>(links, Up, bp, traffic);
    }
    k_readout<<<(NPATHS + 63) / 64, 256, rsmem>>>(D1, b1, D2, b2, Wf, bf, out);
}